// round 1
// baseline (speedup 1.0000x reference)
#include <cuda_runtime.h>
#include <math.h>

#define LQ 13294
#define DMODEL 256
#define MAXN 2

// ---------------- scratch (device globals; no allocation) ----------------
__device__ float g_value[MAXN*LQ*DMODEL];      // [T,256]
__device__ float g_offattn[MAXN*LQ*384];       // [T,384]
__device__ float g_samp[MAXN*LQ*DMODEL];       // [T,256]
__device__ float g_x2[MAXN*LQ*DMODEL];         // [T,256]
__device__ float g_x[MAXN*LQ*DMODEL];          // [T,256]
__device__ float g_hbuf[MAXN*LQ*1024];         // [T,1024]
__device__ float g_fbuf[MAXN*LQ*DMODEL];       // [T,256]
__device__ float g_Wpack[256*384];
__device__ float g_bpack[384];

// ---------------- pack W_off|W_attn into one [256,384] ----------------
__global__ void pack_w_kernel(const float* __restrict__ Woff, const float* __restrict__ Wattn,
                              const float* __restrict__ boff, const float* __restrict__ battn) {
    int i = blockIdx.x * 256 + threadIdx.x;
    if (i < 256 * 384) {
        int k = i / 384, c = i - k * 384;
        g_Wpack[i] = (c < 256) ? Woff[k * 256 + c] : Wattn[k * 128 + (c - 256)];
    }
    if (i < 384) g_bpack[i] = (i < 256) ? boff[i] : battn[i - 256];
}

// ---------------- classic 128x128x8 SIMT fp32 GEMM ----------------
// C[M,N] = (A (+ A2)) @ B + bias, optional ReLU. B is [K,N] row-major.
// N must be a multiple of 128 (holds: 256, 384, 1024). K multiple of 8.
template<bool ADD2, bool RELU>
__global__ void __launch_bounds__(256) sgemm_kernel(
    const float* __restrict__ A, const float* __restrict__ A2,
    const float* __restrict__ B, const float* __restrict__ bias,
    float* __restrict__ C, int M, int N, int K)
{
    __shared__ float As[8][128];
    __shared__ float Bs[8][128];
    const int tid = threadIdx.x;
    const int bm = blockIdx.y * 128;
    const int bn = blockIdx.x * 128;

    const int arow = tid >> 1;           // 0..127
    const int acol = (tid & 1) * 4;      // 0 or 4
    const int brow = tid >> 5;           // 0..7
    const int bcol = (tid & 31) * 4;     // 0..124

    const int ty = tid >> 4;             // 0..15
    const int tx = tid & 15;             // 0..15

    float acc[8][8];
    #pragma unroll
    for (int i = 0; i < 8; i++)
        #pragma unroll
        for (int j = 0; j < 8; j++) acc[i][j] = 0.f;

    for (int k0 = 0; k0 < K; k0 += 8) {
        float4 av = make_float4(0.f, 0.f, 0.f, 0.f);
        int gr = bm + arow;
        if (gr < M) {
            av = *(const float4*)(A + (size_t)gr * K + k0 + acol);
            if (ADD2) {
                float4 a2 = *(const float4*)(A2 + (size_t)gr * K + k0 + acol);
                av.x += a2.x; av.y += a2.y; av.z += a2.z; av.w += a2.w;
            }
        }
        As[acol + 0][arow] = av.x;
        As[acol + 1][arow] = av.y;
        As[acol + 2][arow] = av.z;
        As[acol + 3][arow] = av.w;

        float4 bv = *(const float4*)(B + (size_t)(k0 + brow) * N + bn + bcol);
        *(float4*)&Bs[brow][bcol] = bv;

        __syncthreads();

        #pragma unroll
        for (int kk = 0; kk < 8; kk++) {
            float4 a0 = *(const float4*)&As[kk][ty * 8 + 0];
            float4 a1 = *(const float4*)&As[kk][ty * 8 + 4];
            float4 b0 = *(const float4*)&Bs[kk][tx * 8 + 0];
            float4 b1 = *(const float4*)&Bs[kk][tx * 8 + 4];
            float af[8] = {a0.x, a0.y, a0.z, a0.w, a1.x, a1.y, a1.z, a1.w};
            float bf[8] = {b0.x, b0.y, b0.z, b0.w, b1.x, b1.y, b1.z, b1.w};
            #pragma unroll
            for (int i = 0; i < 8; i++)
                #pragma unroll
                for (int j = 0; j < 8; j++)
                    acc[i][j] = fmaf(af[i], bf[j], acc[i][j]);
        }
        __syncthreads();
    }

    // epilogue
    const int gn0 = bn + tx * 8;
    float bb[8];
    #pragma unroll
    for (int j = 0; j < 8; j++) bb[j] = bias[gn0 + j];

    #pragma unroll
    for (int i = 0; i < 8; i++) {
        int gm = bm + ty * 8 + i;
        if (gm >= M) continue;
        float v[8];
        #pragma unroll
        for (int j = 0; j < 8; j++) {
            v[j] = acc[i][j] + bb[j];
            if (RELU) v[j] = fmaxf(v[j], 0.f);
        }
        *(float4*)(C + (size_t)gm * N + gn0 + 0) = make_float4(v[0], v[1], v[2], v[3]);
        *(float4*)(C + (size_t)gm * N + gn0 + 4) = make_float4(v[4], v[5], v[6], v[7]);
    }
}

// ---------------- deformable sampling: one warp per (token, head) ----------------
__global__ void __launch_bounds__(256) sample_kernel(const float* __restrict__ rp, int T)
{
    int t = blockIdx.x;
    if (t >= T) return;
    const int h = threadIdx.x >> 5;
    const int lane = threadIdx.x & 31;

    const float* raw = g_offattn + (size_t)t * 384;
    // offsets: lane i holds raw[h*32 + i]  (layout l*8 + p*2 + c)
    float offv = raw[h * 32 + lane];
    // attn logits: lanes 0..15
    float av = (lane < 16) ? raw[256 + h * 16 + lane] : -1e30f;
    float m = av;
    #pragma unroll
    for (int o = 16; o; o >>= 1) m = fmaxf(m, __shfl_xor_sync(0xffffffffu, m, o));
    float e = (lane < 16) ? __expf(av - m) : 0.f;
    float s = e;
    #pragma unroll
    for (int o = 16; o; o >>= 1) s += __shfl_xor_sync(0xffffffffu, s, o);
    float anorm = e / s;

    // reference points: lanes 0..7 hold rp[t*8 + lane]  (layout l*2 + c)
    float refv = (lane < 8) ? rp[(size_t)t * 8 + lane] : 0.f;

    const int LSa[4] = {0, 10000, 12500, 13125};
    const int Wla[4] = {100, 50, 25, 13};
    const int Hla[4] = {100, 50, 25, 13};

    const int n = t / LQ;
    const float* vb = g_value + ((size_t)n * LQ) * 256 + h * 32 + lane;

    float acc = 0.f;
    #pragma unroll
    for (int p = 0; p < 16; p++) {
        const int l = p >> 2;
        float rx = __shfl_sync(0xffffffffu, refv, 2 * l);
        float ry = __shfl_sync(0xffffffffu, refv, 2 * l + 1);
        float ox = __shfl_sync(0xffffffffu, offv, 2 * p);
        float oy = __shfl_sync(0xffffffffu, offv, 2 * p + 1);
        float aw = __shfl_sync(0xffffffffu, anorm, p);

        const int Wi = Wla[l], Hi = Hla[l];
        // loc = ref + off/normalizer; x = loc.x*W - 0.5 = ref.x*W + off.x - 0.5
        float x = rx * (float)Wi + ox - 0.5f;
        float y = ry * (float)Hi + oy - 0.5f;
        float xf = floorf(x), yf = floorf(y);
        int x0 = (int)xf, y0 = (int)yf;
        float wx1 = x - xf, wy1 = y - yf;
        float wx0 = 1.f - wx1, wy0 = 1.f - wy1;

        const float* vl = vb + (size_t)LSa[l] * 256;
        #pragma unroll
        for (int tap = 0; tap < 4; tap++) {
            int dx = tap & 1, dy = tap >> 1;
            int xi = x0 + dx, yi = y0 + dy;
            if (xi >= 0 && xi < Wi && yi >= 0 && yi < Hi) {
                float w = (dx ? wx1 : wx0) * (dy ? wy1 : wy0);
                acc = fmaf(aw * w, __ldg(vl + (size_t)(yi * Wi + xi) * 256), acc);
            }
        }
    }
    g_samp[(size_t)t * 256 + h * 32 + lane] = acc;
}

// ---------------- LayerNorm over 256 channels: out = LN(a+b)*g + be ----------------
__global__ void __launch_bounds__(256) ln_kernel(
    const float* __restrict__ a, const float* __restrict__ b,
    const float* __restrict__ g, const float* __restrict__ be,
    float* __restrict__ out)
{
    const int t = blockIdx.x;
    const int c = threadIdx.x;
    const size_t i = (size_t)t * 256 + c;
    float v = a[i] + b[i];
    float s = v, s2 = v * v;
    #pragma unroll
    for (int o = 16; o; o >>= 1) {
        s  += __shfl_xor_sync(0xffffffffu, s,  o);
        s2 += __shfl_xor_sync(0xffffffffu, s2, o);
    }
    __shared__ float rs[8], rs2[8];
    __shared__ float sh_mean, sh_rstd;
    const int w = c >> 5;
    if ((c & 31) == 0) { rs[w] = s; rs2[w] = s2; }
    __syncthreads();
    if (c == 0) {
        float S = 0.f, S2 = 0.f;
        #pragma unroll
        for (int k = 0; k < 8; k++) { S += rs[k]; S2 += rs2[k]; }
        float mu = S * (1.f / 256.f);
        float var = S2 * (1.f / 256.f) - mu * mu;
        sh_mean = mu;
        sh_rstd = rsqrtf(var + 1e-5f);
    }
    __syncthreads();
    out[i] = (v - sh_mean) * sh_rstd * g[c] + be[c];
}

// ---------------- host launcher ----------------
extern "C" void kernel_launch(void* const* d_in, const int* in_sizes, int n_in,
                              void* d_out, int out_size)
{
    const float* src   = (const float*)d_in[0];
    const float* pos   = (const float*)d_in[1];
    const float* rp    = (const float*)d_in[2];
    // d_in[3] spatial_shapes, d_in[4] level_start_index: static, hardcoded
    const float* Wv    = (const float*)d_in[5];
    const float* bv    = (const float*)d_in[6];
    const float* Woff  = (const float*)d_in[7];
    const float* boff  = (const float*)d_in[8];
    const float* Wattn = (const float*)d_in[9];
    const float* battn = (const float*)d_in[10];
    const float* Wout  = (const float*)d_in[11];
    const float* bout  = (const float*)d_in[12];
    const float* W1    = (const float*)d_in[13];
    const float* b1    = (const float*)d_in[14];
    const float* W2    = (const float*)d_in[15];
    const float* b2    = (const float*)d_in[16];
    const float* g1    = (const float*)d_in[17];
    const float* be1   = (const float*)d_in[18];
    const float* g2    = (const float*)d_in[19];
    const float* be2   = (const float*)d_in[20];

    const int T = in_sizes[0] / DMODEL;   // N * Lq

    float *p_value, *p_offattn, *p_samp, *p_x2, *p_x, *p_h, *p_f, *p_Wpack, *p_bpack;
    cudaGetSymbolAddress((void**)&p_value,   g_value);
    cudaGetSymbolAddress((void**)&p_offattn, g_offattn);
    cudaGetSymbolAddress((void**)&p_samp,    g_samp);
    cudaGetSymbolAddress((void**)&p_x2,      g_x2);
    cudaGetSymbolAddress((void**)&p_x,       g_x);
    cudaGetSymbolAddress((void**)&p_h,       g_hbuf);
    cudaGetSymbolAddress((void**)&p_f,       g_fbuf);
    cudaGetSymbolAddress((void**)&p_Wpack,   g_Wpack);
    cudaGetSymbolAddress((void**)&p_bpack,   g_bpack);

    const int MB = (T + 127) / 128;

    // 0. pack off/attn weights into one GEMM
    pack_w_kernel<<<384, 256>>>(Woff, Wattn, boff, battn);

    // 1. value = src @ Wv + bv
    sgemm_kernel<false, false><<<dim3(2, MB), 256>>>(src, src, Wv, bv, p_value, T, 256, 256);

    // 2. offattn = (src + pos) @ [W_off | W_attn] + [b_off | b_attn]
    sgemm_kernel<true, false><<<dim3(3, MB), 256>>>(src, pos, p_Wpack, p_bpack, p_offattn, T, 384, 256);

    // 3. deformable sampling + softmax fused
    sample_kernel<<<T, 256>>>(rp, T);

    // 4. x2 = samp @ W_out + b_out
    sgemm_kernel<false, false><<<dim3(2, MB), 256>>>(p_samp, p_samp, Wout, bout, p_x2, T, 256, 256);

    // 5. x = LN(src + x2)
    ln_kernel<<<T, 256>>>(src, p_x2, g1, be1, p_x);

    // 6. h = relu(x @ W1 + b1)
    sgemm_kernel<false, true><<<dim3(8, MB), 256>>>(p_x, p_x, W1, b1, p_h, T, 1024, 256);

    // 7. f = h @ W2 + b2
    sgemm_kernel<false, false><<<dim3(2, MB), 256>>>(p_h, p_h, W2, b2, p_f, T, 256, 1024);

    // 8. out = LN(x + f)
    ln_kernel<<<T, 256>>>(p_x, p_f, g2, be2, (float*)d_out);
}

// round 2
// speedup vs baseline: 2.2626x; 2.2626x over previous
#include <cuda_runtime.h>
#include <math.h>
#include <stdint.h>

#define LQ 13294
#define DMODEL 256
#define MAXN 2

// ---------------- scratch (device globals; no allocation) ----------------
__device__ float g_value[MAXN*LQ*DMODEL];      // [T,256]
__device__ float g_offattn[MAXN*LQ*384];       // [T,384]
__device__ float g_samp[MAXN*LQ*DMODEL];       // [T,256]
__device__ float g_x2[MAXN*LQ*DMODEL];         // [T,256]
__device__ float g_x[MAXN*LQ*DMODEL];          // [T,256]
__device__ float g_hbuf[MAXN*LQ*1024];         // [T,1024]
__device__ float g_fbuf[MAXN*LQ*DMODEL];       // [T,256]
__device__ float g_Wpack[256*384];
__device__ float g_bpack[384];

// ---------------- pack W_off|W_attn into one [256,384] ----------------
__global__ void pack_w_kernel(const float* __restrict__ Woff, const float* __restrict__ Wattn,
                              const float* __restrict__ boff, const float* __restrict__ battn) {
    int i = blockIdx.x * 256 + threadIdx.x;
    if (i < 256 * 384) {
        int k = i / 384, c = i - k * 384;
        g_Wpack[i] = (c < 256) ? Woff[k * 256 + c] : Wattn[k * 128 + (c - 256)];
    }
    if (i < 384) g_bpack[i] = (i < 256) ? boff[i] : battn[i - 256];
}

// ---------------- tf32 tensor-core GEMM ----------------
// C[M,N] = (A (+ A2)) @ B + bias, optional ReLU. B is [K,N] row-major.
// BM=128, BN=64, BK=32, 256 threads, warp grid 4(M)x2(N), warp tile 32x32.
// N must be multiple of 64, K multiple of 32.

__device__ __forceinline__ float to_tf32(float x) {
    uint32_t u;
    asm("cvt.rna.tf32.f32 %0, %1;" : "=r"(u) : "f"(x));
    return __uint_as_float(u);
}

__device__ __forceinline__ void mma_tf32(float* d, const uint32_t* a, const uint32_t* b) {
    asm volatile(
        "mma.sync.aligned.m16n8k8.row.col.f32.tf32.tf32.f32 "
        "{%0,%1,%2,%3}, {%4,%5,%6,%7}, {%8,%9}, {%0,%1,%2,%3};\n"
        : "+f"(d[0]), "+f"(d[1]), "+f"(d[2]), "+f"(d[3])
        : "r"(a[0]), "r"(a[1]), "r"(a[2]), "r"(a[3]), "r"(b[0]), "r"(b[1]));
}

#define ASTRIDE 36
#define BSTRIDE 72

template<bool ADD2, bool RELU>
__global__ void __launch_bounds__(256) tgemm_kernel(
    const float* __restrict__ A, const float* __restrict__ A2,
    const float* __restrict__ B, const float* __restrict__ bias,
    float* __restrict__ C, int M, int N, int K)
{
    __shared__ float As[128][ASTRIDE];
    __shared__ float Bs[32][BSTRIDE];

    const int tid = threadIdx.x;
    const int bm = blockIdx.y * 128;
    const int bn = blockIdx.x * 64;
    const int wid = tid >> 5;
    const int lane = tid & 31;
    const int wm = (wid & 3) * 32;
    const int wn = (wid >> 2) * 32;
    const int r = lane >> 2;
    const int c = lane & 3;

    float acc[2][4][4];
    #pragma unroll
    for (int i = 0; i < 2; i++)
        #pragma unroll
        for (int j = 0; j < 4; j++)
            #pragma unroll
            for (int k = 0; k < 4; k++) acc[i][j][k] = 0.f;

    // global load slots
    const int arow = tid >> 1;            // A: 4 float4/thread: rows tid>>1 variant below
    const int ktiles = K >> 5;

    float4 pa[4], pb[2];

    // ---- prologue: load k-tile 0 straight to smem ----
    #pragma unroll
    for (int i = 0; i < 4; i++) {
        int idx = tid + i * 256;
        int row = idx >> 3, c4 = idx & 7;
        int gr = bm + row;
        float4 v = make_float4(0.f, 0.f, 0.f, 0.f);
        if (gr < M) {
            v = *(const float4*)(A + (size_t)gr * K + c4 * 4);
            if (ADD2) {
                float4 v2 = *(const float4*)(A2 + (size_t)gr * K + c4 * 4);
                v.x += v2.x; v.y += v2.y; v.z += v2.z; v.w += v2.w;
            }
        }
        As[row][c4 * 4 + 0] = to_tf32(v.x);
        As[row][c4 * 4 + 1] = to_tf32(v.y);
        As[row][c4 * 4 + 2] = to_tf32(v.z);
        As[row][c4 * 4 + 3] = to_tf32(v.w);
    }
    #pragma unroll
    for (int i = 0; i < 2; i++) {
        int idx = tid + i * 256;
        int row = idx >> 4, c4 = idx & 15;
        float4 v = *(const float4*)(B + (size_t)row * N + bn + c4 * 4);
        Bs[row][c4 * 4 + 0] = to_tf32(v.x);
        Bs[row][c4 * 4 + 1] = to_tf32(v.y);
        Bs[row][c4 * 4 + 2] = to_tf32(v.z);
        Bs[row][c4 * 4 + 3] = to_tf32(v.w);
    }
    __syncthreads();

    for (int kt = 0; kt < ktiles; kt++) {
        const bool has_next = (kt + 1 < ktiles);
        if (has_next) {
            const int kk = (kt + 1) * 32;
            #pragma unroll
            for (int i = 0; i < 4; i++) {
                int idx = tid + i * 256;
                int row = idx >> 3, c4 = idx & 7;
                int gr = bm + row;
                float4 v = make_float4(0.f, 0.f, 0.f, 0.f);
                if (gr < M) {
                    v = *(const float4*)(A + (size_t)gr * K + kk + c4 * 4);
                    if (ADD2) {
                        float4 v2 = *(const float4*)(A2 + (size_t)gr * K + kk + c4 * 4);
                        v.x += v2.x; v.y += v2.y; v.z += v2.z; v.w += v2.w;
                    }
                }
                pa[i] = v;
            }
            #pragma unroll
            for (int i = 0; i < 2; i++) {
                int idx = tid + i * 256;
                int row = idx >> 4, c4 = idx & 15;
                pb[i] = *(const float4*)(B + (size_t)(kk + row) * N + bn + c4 * 4);
            }
        }

        // ---- compute this tile ----
        #pragma unroll
        for (int ks = 0; ks < 4; ks++) {
            const int k0 = ks * 8;
            uint32_t af[2][4], bf[4][2];
            #pragma unroll
            for (int mt = 0; mt < 2; mt++) {
                int rb = wm + mt * 16 + r;
                af[mt][0] = __float_as_uint(As[rb][k0 + c]);
                af[mt][1] = __float_as_uint(As[rb + 8][k0 + c]);
                af[mt][2] = __float_as_uint(As[rb][k0 + c + 4]);
                af[mt][3] = __float_as_uint(As[rb + 8][k0 + c + 4]);
            }
            #pragma unroll
            for (int nt = 0; nt < 4; nt++) {
                int cb = wn + nt * 8 + r;
                bf[nt][0] = __float_as_uint(Bs[k0 + c][cb]);
                bf[nt][1] = __float_as_uint(Bs[k0 + c + 4][cb]);
            }
            #pragma unroll
            for (int mt = 0; mt < 2; mt++)
                #pragma unroll
                for (int nt = 0; nt < 4; nt++)
                    mma_tf32(acc[mt][nt], af[mt], bf[nt]);
        }
        __syncthreads();

        if (has_next) {
            #pragma unroll
            for (int i = 0; i < 4; i++) {
                int idx = tid + i * 256;
                int row = idx >> 3, c4 = idx & 7;
                As[row][c4 * 4 + 0] = to_tf32(pa[i].x);
                As[row][c4 * 4 + 1] = to_tf32(pa[i].y);
                As[row][c4 * 4 + 2] = to_tf32(pa[i].z);
                As[row][c4 * 4 + 3] = to_tf32(pa[i].w);
            }
            #pragma unroll
            for (int i = 0; i < 2; i++) {
                int idx = tid + i * 256;
                int row = idx >> 4, c4 = idx & 15;
                Bs[row][c4 * 4 + 0] = to_tf32(pb[i].x);
                Bs[row][c4 * 4 + 1] = to_tf32(pb[i].y);
                Bs[row][c4 * 4 + 2] = to_tf32(pb[i].z);
                Bs[row][c4 * 4 + 3] = to_tf32(pb[i].w);
            }
            __syncthreads();
        }
    }

    // ---- epilogue ----
    #pragma unroll
    for (int mt = 0; mt < 2; mt++) {
        #pragma unroll
        for (int nt = 0; nt < 4; nt++) {
            int col = bn + wn + nt * 8 + 2 * c;
            float b0 = bias[col], b1 = bias[col + 1];
            int row0 = bm + wm + mt * 16 + r;
            if (row0 < M) {
                float v0 = acc[mt][nt][0] + b0;
                float v1 = acc[mt][nt][1] + b1;
                if (RELU) { v0 = fmaxf(v0, 0.f); v1 = fmaxf(v1, 0.f); }
                *(float2*)(C + (size_t)row0 * N + col) = make_float2(v0, v1);
            }
            int row1 = row0 + 8;
            if (row1 < M) {
                float v2 = acc[mt][nt][2] + b0;
                float v3 = acc[mt][nt][3] + b1;
                if (RELU) { v2 = fmaxf(v2, 0.f); v3 = fmaxf(v3, 0.f); }
                *(float2*)(C + (size_t)row1 * N + col) = make_float2(v2, v3);
            }
        }
    }
}

// ---------------- deformable sampling: one warp per (token, head) ----------------
// Lane p<16 precomputes point p's 4 clamped gather indices + combined weights once;
// the gather loop is shuffles + coalesced 128B loads + FMAs.
__global__ void __launch_bounds__(256) sample_kernel(const float* __restrict__ rp, int T)
{
    const int t = blockIdx.x;
    if (t >= T) return;
    const int h = threadIdx.x >> 5;
    const int lane = threadIdx.x & 31;
    const unsigned FULL = 0xffffffffu;

    const float* raw = g_offattn + (size_t)t * 384;
    float offv = raw[h * 32 + lane];
    float av = (lane < 16) ? raw[256 + h * 16 + lane] : -1e30f;
    float m = av;
    #pragma unroll
    for (int o = 16; o; o >>= 1) m = fmaxf(m, __shfl_xor_sync(FULL, m, o));
    float e = (lane < 16) ? __expf(av - m) : 0.f;
    float s = e;
    #pragma unroll
    for (int o = 16; o; o >>= 1) s += __shfl_xor_sync(FULL, s, o);
    const float anorm = e / s;   // this lane's own point weight (lane == point id)

    float refv = (lane < 8) ? rp[(size_t)t * 8 + lane] : 0.f;

    const int LSa[4] = {0, 10000, 12500, 13125};
    const int Wla[4] = {100, 50, 25, 13};

    // ---- per-point precompute on lane p (p = lane, valid for p<16) ----
    const int p = lane;
    const int l = (p >> 2) & 3;
    const int Wi = Wla[l], Hi = Wla[l];
    float rx = __shfl_sync(FULL, refv, 2 * l);
    float ry = __shfl_sync(FULL, refv, 2 * l + 1);
    float ox = __shfl_sync(FULL, offv, (2 * p) & 31);
    float oy = __shfl_sync(FULL, offv, (2 * p + 1) & 31);

    float x = rx * (float)Wi + ox - 0.5f;
    float y = ry * (float)Wi + oy - 0.5f;   // Hi == Wi for all levels here
    float xf = floorf(x), yf = floorf(y);
    int x0 = (int)xf, y0 = (int)yf;
    float wx1 = x - xf, wy1 = y - yf;
    float wx0 = 1.f - wx1, wy0 = 1.f - wy1;

    int   idxs[4];
    float ws[4];
    #pragma unroll
    for (int tap = 0; tap < 4; tap++) {
        int dx = tap & 1, dy = tap >> 1;
        int xi = x0 + dx, yi = y0 + dy;
        bool valid = (xi >= 0) & (xi < Wi) & (yi >= 0) & (yi < Hi);
        float w = (dx ? wx1 : wx0) * (dy ? wy1 : wy0) * anorm;
        int xic = min(max(xi, 0), Wi - 1);
        int yic = min(max(yi, 0), Hi - 1);
        idxs[tap] = LSa[l] + yic * Wi + xic;
        ws[tap] = valid ? w : 0.f;
    }

    const int n = (t >= LQ) ? 1 : 0;
    const float* vbase = g_value + ((size_t)n * LQ) * 256 + h * 32 + lane;

    float acc = 0.f;
    #pragma unroll
    for (int q = 0; q < 16; q++) {
        #pragma unroll
        for (int tap = 0; tap < 4; tap++) {
            int ii = __shfl_sync(FULL, idxs[tap], q);
            float w = __shfl_sync(FULL, ws[tap], q);
            acc = fmaf(w, __ldg(vbase + (size_t)ii * 256), acc);
        }
    }
    g_samp[(size_t)t * 256 + h * 32 + lane] = acc;
}

// ---------------- LayerNorm over 256 channels: out = LN(a+b)*g + be ----------------
__global__ void __launch_bounds__(256) ln_kernel(
    const float* __restrict__ a, const float* __restrict__ b,
    const float* __restrict__ g, const float* __restrict__ be,
    float* __restrict__ out)
{
    const int t = blockIdx.x;
    const int c = threadIdx.x;
    const size_t i = (size_t)t * 256 + c;
    float v = a[i] + b[i];
    float s = v, s2 = v * v;
    #pragma unroll
    for (int o = 16; o; o >>= 1) {
        s  += __shfl_xor_sync(0xffffffffu, s,  o);
        s2 += __shfl_xor_sync(0xffffffffu, s2, o);
    }
    __shared__ float rs[8], rs2[8];
    __shared__ float sh_mean, sh_rstd;
    const int w = c >> 5;
    if ((c & 31) == 0) { rs[w] = s; rs2[w] = s2; }
    __syncthreads();
    if (c == 0) {
        float S = 0.f, S2 = 0.f;
        #pragma unroll
        for (int k = 0; k < 8; k++) { S += rs[k]; S2 += rs2[k]; }
        float mu = S * (1.f / 256.f);
        float var = S2 * (1.f / 256.f) - mu * mu;
        sh_mean = mu;
        sh_rstd = rsqrtf(var + 1e-5f);
    }
    __syncthreads();
    out[i] = (v - sh_mean) * sh_rstd * g[c] + be[c];
}

// ---------------- host launcher ----------------
extern "C" void kernel_launch(void* const* d_in, const int* in_sizes, int n_in,
                              void* d_out, int out_size)
{
    const float* src   = (const float*)d_in[0];
    const float* pos   = (const float*)d_in[1];
    const float* rp    = (const float*)d_in[2];
    const float* Wv    = (const float*)d_in[5];
    const float* bv    = (const float*)d_in[6];
    const float* Woff  = (const float*)d_in[7];
    const float* boff  = (const float*)d_in[8];
    const float* Wattn = (const float*)d_in[9];
    const float* battn = (const float*)d_in[10];
    const float* Wout  = (const float*)d_in[11];
    const float* bout  = (const float*)d_in[12];
    const float* W1    = (const float*)d_in[13];
    const float* b1    = (const float*)d_in[14];
    const float* W2    = (const float*)d_in[15];
    const float* b2    = (const float*)d_in[16];
    const float* g1    = (const float*)d_in[17];
    const float* be1   = (const float*)d_in[18];
    const float* g2    = (const float*)d_in[19];
    const float* be2   = (const float*)d_in[20];

    const int T = in_sizes[0] / DMODEL;   // N * Lq

    float *p_value, *p_offattn, *p_samp, *p_x2, *p_x, *p_h, *p_f, *p_Wpack, *p_bpack;
    cudaGetSymbolAddress((void**)&p_value,   g_value);
    cudaGetSymbolAddress((void**)&p_offattn, g_offattn);
    cudaGetSymbolAddress((void**)&p_samp,    g_samp);
    cudaGetSymbolAddress((void**)&p_x2,      g_x2);
    cudaGetSymbolAddress((void**)&p_x,       g_x);
    cudaGetSymbolAddress((void**)&p_h,       g_hbuf);
    cudaGetSymbolAddress((void**)&p_f,       g_fbuf);
    cudaGetSymbolAddress((void**)&p_Wpack,   g_Wpack);
    cudaGetSymbolAddress((void**)&p_bpack,   g_bpack);

    const int MB = (T + 127) / 128;

    pack_w_kernel<<<384, 256>>>(Woff, Wattn, boff, battn);

    // 1. value = src @ Wv + bv
    tgemm_kernel<false, false><<<dim3(4, MB), 256>>>(src, src, Wv, bv, p_value, T, 256, 256);

    // 2. offattn = (src + pos) @ [W_off | W_attn] + [b_off | b_attn]
    tgemm_kernel<true, false><<<dim3(6, MB), 256>>>(src, pos, p_Wpack, p_bpack, p_offattn, T, 384, 256);

    // 3. deformable sampling + softmax fused
    sample_kernel<<<T, 256>>>(rp, T);

    // 4. x2 = samp @ W_out + b_out
    tgemm_kernel<false, false><<<dim3(4, MB), 256>>>(p_samp, p_samp, Wout, bout, p_x2, T, 256, 256);

    // 5. x = LN(src + x2)
    ln_kernel<<<T, 256>>>(src, p_x2, g1, be1, p_x);

    // 6. h = relu(x @ W1 + b1)
    tgemm_kernel<false, true><<<dim3(16, MB), 256>>>(p_x, p_x, W1, b1, p_h, T, 1024, 256);

    // 7. f = h @ W2 + b2
    tgemm_kernel<false, false><<<dim3(4, MB), 256>>>(p_h, p_h, W2, b2, p_f, T, 256, 1024);

    // 8. out = LN(x + f)
    ln_kernel<<<T, 256>>>(p_x, p_f, g2, be2, (float*)d_out);
}

// round 3
// speedup vs baseline: 2.4507x; 1.0831x over previous
#include <cuda_runtime.h>
#include <math.h>
#include <stdint.h>

#define LQ 13294
#define DMODEL 256
#define MAXN 2

// ---------------- scratch (device globals; no allocation) ----------------
__device__ float g_value[MAXN*LQ*DMODEL];      // [T,256]
__device__ float g_q[MAXN*LQ*DMODEL];          // [T,256] src+pos
__device__ float g_offattn[MAXN*LQ*384];       // [T,384]
__device__ float g_samp[MAXN*LQ*DMODEL];       // [T,256]
__device__ float g_x2[MAXN*LQ*DMODEL];         // [T,256]
__device__ float g_x[MAXN*LQ*DMODEL];          // [T,256]
__device__ float g_hbuf[MAXN*LQ*1024];         // [T,1024]
__device__ float g_fbuf[MAXN*LQ*DMODEL];       // [T,256]
__device__ float g_Wpack[256*384];
__device__ float g_bpack[384];

// ---------------- pack W_off|W_attn into one [256,384] ----------------
__global__ void pack_w_kernel(const float* __restrict__ Woff, const float* __restrict__ Wattn,
                              const float* __restrict__ boff, const float* __restrict__ battn) {
    int i = blockIdx.x * 256 + threadIdx.x;
    if (i < 256 * 384) {
        int k = i / 384, c = i - k * 384;
        g_Wpack[i] = (c < 256) ? Woff[k * 256 + c] : Wattn[k * 128 + (c - 256)];
    }
    if (i < 384) g_bpack[i] = (i < 256) ? boff[i] : battn[i - 256];
}

// ---------------- q = src + pos (float4) ----------------
__global__ void add_kernel(const float* __restrict__ a, const float* __restrict__ b,
                           float* __restrict__ o, int n4) {
    int i = blockIdx.x * blockDim.x + threadIdx.x;
    if (i < n4) {
        float4 va = ((const float4*)a)[i];
        float4 vb = ((const float4*)b)[i];
        ((float4*)o)[i] = make_float4(va.x + vb.x, va.y + vb.y, va.z + vb.z, va.w + vb.w);
    }
}

// ---------------- tf32 tensor-core GEMM with cp.async double buffer ----------------
// C[M,N] = A @ B + bias, optional ReLU. B is [K,N] row-major.
// BM=128, BN=64, BK=32, 256 threads, warp grid 4(M)x2(N), warp tile 32x32.

__device__ __forceinline__ void mma_tf32(float* d, const uint32_t* a, const uint32_t* b) {
    asm volatile(
        "mma.sync.aligned.m16n8k8.row.col.f32.tf32.tf32.f32 "
        "{%0,%1,%2,%3}, {%4,%5,%6,%7}, {%8,%9}, {%0,%1,%2,%3};\n"
        : "+f"(d[0]), "+f"(d[1]), "+f"(d[2]), "+f"(d[3])
        : "r"(a[0]), "r"(a[1]), "r"(a[2]), "r"(a[3]), "r"(b[0]), "r"(b[1]));
}

__device__ __forceinline__ void cp_async16(uint32_t saddr, const void* gptr, int srcbytes) {
    asm volatile("cp.async.cg.shared.global [%0], [%1], 16, %2;\n"
                 :: "r"(saddr), "l"(gptr), "r"(srcbytes));
}
__device__ __forceinline__ void cp_commit() { asm volatile("cp.async.commit_group;\n"); }
template<int N>
__device__ __forceinline__ void cp_wait() { asm volatile("cp.async.wait_group %0;\n" :: "n"(N)); }

#define ASTRIDE 36
#define BSTRIDE 72

template<bool RELU>
__global__ void __launch_bounds__(256) tgemm_kernel(
    const float* __restrict__ A, const float* __restrict__ B,
    const float* __restrict__ bias, float* __restrict__ C,
    int M, int N, int K)
{
    __shared__ float As[2][128][ASTRIDE];
    __shared__ float Bs[2][32][BSTRIDE];

    const int tid = threadIdx.x;
    const int bm = blockIdx.y * 128;
    const int bn = blockIdx.x * 64;
    const int wid = tid >> 5;
    const int lane = tid & 31;
    const int wm = (wid & 3) * 32;
    const int wn = (wid >> 2) * 32;
    const int r = lane >> 2;
    const int c = lane & 3;

    // load geometry
    const int a_row = tid >> 1;           // 0..127, 2 threads per row
    const int a_c4  = (tid & 1) * 2;      // chunk pair base (each thread does chunks a_c4, a_c4+... )
    // A: 128 rows x 32 floats = 128 rows x 8 chunks(16B) = 1024 chunks; 256 thr -> 4 chunks each
    // map: thread does rows tid>>1 with chunks (tid&1)*4 .. +3
    const int b_row = tid >> 4;           // 0..15 (x2 iters -> 32 rows)
    const int b_c4  = tid & 15;           // 0..15 chunks of 16B across 64 floats=16 chunks

    float acc[2][4][4];
    #pragma unroll
    for (int i = 0; i < 2; i++)
        #pragma unroll
        for (int j = 0; j < 4; j++)
            #pragma unroll
            for (int k = 0; k < 4; k++) acc[i][j][k] = 0.f;

    const int ktiles = K >> 5;

    uint32_t sA = (uint32_t)__cvta_generic_to_shared(&As[0][0][0]);
    uint32_t sB = (uint32_t)__cvta_generic_to_shared(&Bs[0][0][0]);
    const uint32_t stageA = 128 * ASTRIDE * 4;
    const uint32_t stageB = 32 * BSTRIDE * 4;

    // ---- issue loads for a k-tile into stage s ----
    auto issue_tile = [&](int kt, int s) {
        const int kk = kt * 32;
        // A
        #pragma unroll
        for (int i = 0; i < 4; i++) {
            int chunk = a_c4 * 2 + i;     // 0..7 within row? need 4 chunks per thread pair layout:
            // thread (tid&1)==0 -> chunks 0..3 ; ==1 -> chunks 4..7
            int cc = (tid & 1) * 4 + i;
            int gr = bm + a_row;
            const float* gp = A + (size_t)gr * K + kk + cc * 4;
            uint32_t dst = sA + s * stageA + (a_row * ASTRIDE + cc * 4) * 4;
            cp_async16(dst, gp, (gr < M) ? 16 : 0);
            (void)chunk;
        }
        // B: 32 rows x 16 chunks = 512 chunks / 256 thr = 2 each
        #pragma unroll
        for (int i = 0; i < 2; i++) {
            int row = b_row + i * 16;
            const float* gp = B + (size_t)(kk + row) * N + bn + b_c4 * 4;
            uint32_t dst = sB + s * stageB + (row * BSTRIDE + b_c4 * 4) * 4;
            cp_async16(dst, gp, 16);
        }
        cp_commit();
    };

    issue_tile(0, 0);

    for (int kt = 0; kt < ktiles; kt++) {
        const int cur = kt & 1;
        const bool has_next = (kt + 1 < ktiles);
        if (has_next) issue_tile(kt + 1, cur ^ 1);

        if (has_next) cp_wait<1>(); else cp_wait<0>();
        __syncthreads();

        #pragma unroll
        for (int ks = 0; ks < 4; ks++) {
            const int k0 = ks * 8;
            uint32_t af[2][4], bf[4][2];
            #pragma unroll
            for (int mt = 0; mt < 2; mt++) {
                int rb = wm + mt * 16 + r;
                af[mt][0] = __float_as_uint(As[cur][rb][k0 + c]);
                af[mt][1] = __float_as_uint(As[cur][rb + 8][k0 + c]);
                af[mt][2] = __float_as_uint(As[cur][rb][k0 + c + 4]);
                af[mt][3] = __float_as_uint(As[cur][rb + 8][k0 + c + 4]);
            }
            #pragma unroll
            for (int nt = 0; nt < 4; nt++) {
                int cb = wn + nt * 8 + r;
                bf[nt][0] = __float_as_uint(Bs[cur][k0 + c][cb]);
                bf[nt][1] = __float_as_uint(Bs[cur][k0 + c + 4][cb]);
            }
            #pragma unroll
            for (int mt = 0; mt < 2; mt++)
                #pragma unroll
                for (int nt = 0; nt < 4; nt++)
                    mma_tf32(acc[mt][nt], af[mt], bf[nt]);
        }
        __syncthreads();
    }

    // ---- epilogue ----
    #pragma unroll
    for (int mt = 0; mt < 2; mt++) {
        #pragma unroll
        for (int nt = 0; nt < 4; nt++) {
            int col = bn + wn + nt * 8 + 2 * c;
            float b0 = bias[col], b1 = bias[col + 1];
            int row0 = bm + wm + mt * 16 + r;
            if (row0 < M) {
                float v0 = acc[mt][nt][0] + b0;
                float v1 = acc[mt][nt][1] + b1;
                if (RELU) { v0 = fmaxf(v0, 0.f); v1 = fmaxf(v1, 0.f); }
                *(float2*)(C + (size_t)row0 * N + col) = make_float2(v0, v1);
            }
            int row1 = row0 + 8;
            if (row1 < M) {
                float v2 = acc[mt][nt][2] + b0;
                float v3 = acc[mt][nt][3] + b1;
                if (RELU) { v2 = fmaxf(v2, 0.f); v3 = fmaxf(v3, 0.f); }
                *(float2*)(C + (size_t)row1 * N + col) = make_float2(v2, v3);
            }
        }
    }
}

// ---------------- deformable sampling: one warp per (token, head) ----------------
__global__ void __launch_bounds__(256) sample_kernel(const float* __restrict__ rp, int T)
{
    const int t = blockIdx.x;
    if (t >= T) return;
    const int h = threadIdx.x >> 5;
    const int lane = threadIdx.x & 31;
    const unsigned FULL = 0xffffffffu;

    const float* raw = g_offattn + (size_t)t * 384;
    float offv = raw[h * 32 + lane];
    float av = (lane < 16) ? raw[256 + h * 16 + lane] : -1e30f;
    float m = av;
    #pragma unroll
    for (int o = 16; o; o >>= 1) m = fmaxf(m, __shfl_xor_sync(FULL, m, o));
    float e = (lane < 16) ? __expf(av - m) : 0.f;
    float s = e;
    #pragma unroll
    for (int o = 16; o; o >>= 1) s += __shfl_xor_sync(FULL, s, o);
    const float anorm = e / s;

    float refv = (lane < 8) ? rp[(size_t)t * 8 + lane] : 0.f;

    const int LSa[4] = {0, 10000, 12500, 13125};
    const int Wla[4] = {100, 50, 25, 13};

    // per-point precompute on lane p (= lane; valid for p<16)
    const int p = lane;
    const int l = (p >> 2) & 3;
    const int Wi = Wla[l];
    float rx = __shfl_sync(FULL, refv, 2 * l);
    float ry = __shfl_sync(FULL, refv, 2 * l + 1);
    float ox = __shfl_sync(FULL, offv, (2 * p) & 31);
    float oy = __shfl_sync(FULL, offv, (2 * p + 1) & 31);

    float x = rx * (float)Wi + ox - 0.5f;
    float y = ry * (float)Wi + oy - 0.5f;   // H == W for all levels
    float xf = floorf(x), yf = floorf(y);
    int x0 = (int)xf, y0 = (int)yf;
    float wx1 = x - xf, wy1 = y - yf;
    float wx0 = 1.f - wx1, wy0 = 1.f - wy1;

    int   idxs[4];
    float ws[4];
    #pragma unroll
    for (int tap = 0; tap < 4; tap++) {
        int dx = tap & 1, dy = tap >> 1;
        int xi = x0 + dx, yi = y0 + dy;
        bool valid = (xi >= 0) & (xi < Wi) & (yi >= 0) & (yi < Wi);
        float w = (dx ? wx1 : wx0) * (dy ? wy1 : wy0) * anorm;
        int xic = min(max(xi, 0), Wi - 1);
        int yic = min(max(yi, 0), Wi - 1);
        idxs[tap] = LSa[l] + yic * Wi + xic;
        ws[tap] = valid ? w : 0.f;
    }

    const int n = (t >= LQ) ? 1 : 0;
    const float* vbase = g_value + ((size_t)n * LQ) * 256 + h * 32 + lane;

    float acc0 = 0.f, acc1 = 0.f, acc2 = 0.f, acc3 = 0.f;
    #pragma unroll
    for (int q = 0; q < 16; q++) {
        int i0 = __shfl_sync(FULL, idxs[0], q);
        int i1 = __shfl_sync(FULL, idxs[1], q);
        int i2 = __shfl_sync(FULL, idxs[2], q);
        int i3 = __shfl_sync(FULL, idxs[3], q);
        float w0 = __shfl_sync(FULL, ws[0], q);
        float w1 = __shfl_sync(FULL, ws[1], q);
        float w2 = __shfl_sync(FULL, ws[2], q);
        float w3 = __shfl_sync(FULL, ws[3], q);
        float v0 = __ldg(vbase + (size_t)i0 * 256);
        float v1 = __ldg(vbase + (size_t)i1 * 256);
        float v2 = __ldg(vbase + (size_t)i2 * 256);
        float v3 = __ldg(vbase + (size_t)i3 * 256);
        acc0 = fmaf(w0, v0, acc0);
        acc1 = fmaf(w1, v1, acc1);
        acc2 = fmaf(w2, v2, acc2);
        acc3 = fmaf(w3, v3, acc3);
    }
    g_samp[(size_t)t * 256 + h * 32 + lane] = (acc0 + acc1) + (acc2 + acc3);
}

// ---------------- LayerNorm: one warp per token, out = LN(a+b)*g + be ----------------
__global__ void __launch_bounds__(256) ln_kernel(
    const float* __restrict__ a, const float* __restrict__ b,
    const float* __restrict__ g, const float* __restrict__ be,
    float* __restrict__ out, int T)
{
    const int warp = (blockIdx.x * blockDim.x + threadIdx.x) >> 5;
    if (warp >= T) return;
    const int lane = threadIdx.x & 31;
    const size_t base = (size_t)warp * 256 + lane * 8;

    float4 a0 = *(const float4*)(a + base);
    float4 a1 = *(const float4*)(a + base + 4);
    float4 b0 = *(const float4*)(b + base);
    float4 b1 = *(const float4*)(b + base + 4);
    float v[8] = {a0.x + b0.x, a0.y + b0.y, a0.z + b0.z, a0.w + b0.w,
                  a1.x + b1.x, a1.y + b1.y, a1.z + b1.z, a1.w + b1.w};
    float s = 0.f, s2 = 0.f;
    #pragma unroll
    for (int i = 0; i < 8; i++) { s += v[i]; s2 = fmaf(v[i], v[i], s2); }
    #pragma unroll
    for (int o = 16; o; o >>= 1) {
        s  += __shfl_xor_sync(0xffffffffu, s,  o);
        s2 += __shfl_xor_sync(0xffffffffu, s2, o);
    }
    float mu = s * (1.f / 256.f);
    float var = s2 * (1.f / 256.f) - mu * mu;
    float rstd = rsqrtf(var + 1e-5f);

    float4 gg0 = *(const float4*)(g + lane * 8);
    float4 gg1 = *(const float4*)(g + lane * 8 + 4);
    float4 bb0 = *(const float4*)(be + lane * 8);
    float4 bb1 = *(const float4*)(be + lane * 8 + 4);
    float gv[8] = {gg0.x, gg0.y, gg0.z, gg0.w, gg1.x, gg1.y, gg1.z, gg1.w};
    float bv[8] = {bb0.x, bb0.y, bb0.z, bb0.w, bb1.x, bb1.y, bb1.z, bb1.w};
    float o0[8];
    #pragma unroll
    for (int i = 0; i < 8; i++) o0[i] = (v[i] - mu) * rstd * gv[i] + bv[i];
    *(float4*)(out + base)     = make_float4(o0[0], o0[1], o0[2], o0[3]);
    *(float4*)(out + base + 4) = make_float4(o0[4], o0[5], o0[6], o0[7]);
}

// ---------------- host launcher ----------------
extern "C" void kernel_launch(void* const* d_in, const int* in_sizes, int n_in,
                              void* d_out, int out_size)
{
    const float* src   = (const float*)d_in[0];
    const float* pos   = (const float*)d_in[1];
    const float* rp    = (const float*)d_in[2];
    const float* Wv    = (const float*)d_in[5];
    const float* bv    = (const float*)d_in[6];
    const float* Woff  = (const float*)d_in[7];
    const float* boff  = (const float*)d_in[8];
    const float* Wattn = (const float*)d_in[9];
    const float* battn = (const float*)d_in[10];
    const float* Wout  = (const float*)d_in[11];
    const float* bout  = (const float*)d_in[12];
    const float* W1    = (const float*)d_in[13];
    const float* b1    = (const float*)d_in[14];
    const float* W2    = (const float*)d_in[15];
    const float* b2    = (const float*)d_in[16];
    const float* g1    = (const float*)d_in[17];
    const float* be1   = (const float*)d_in[18];
    const float* g2    = (const float*)d_in[19];
    const float* be2   = (const float*)d_in[20];

    const int T = in_sizes[0] / DMODEL;   // N * Lq

    float *p_value, *p_q, *p_offattn, *p_samp, *p_x2, *p_x, *p_h, *p_f, *p_Wpack, *p_bpack;
    cudaGetSymbolAddress((void**)&p_value,   g_value);
    cudaGetSymbolAddress((void**)&p_q,       g_q);
    cudaGetSymbolAddress((void**)&p_offattn, g_offattn);
    cudaGetSymbolAddress((void**)&p_samp,    g_samp);
    cudaGetSymbolAddress((void**)&p_x2,      g_x2);
    cudaGetSymbolAddress((void**)&p_x,       g_x);
    cudaGetSymbolAddress((void**)&p_h,       g_hbuf);
    cudaGetSymbolAddress((void**)&p_f,       g_fbuf);
    cudaGetSymbolAddress((void**)&p_Wpack,   g_Wpack);
    cudaGetSymbolAddress((void**)&p_bpack,   g_bpack);

    const int MB = (T + 127) / 128;
    const int n4 = T * DMODEL / 4;

    pack_w_kernel<<<384, 256>>>(Woff, Wattn, boff, battn);
    add_kernel<<<(n4 + 255) / 256, 256>>>(src, pos, p_q, n4);

    // 1. value = src @ Wv + bv
    tgemm_kernel<false><<<dim3(4, MB), 256>>>(src, Wv, bv, p_value, T, 256, 256);

    // 2. offattn = q @ [W_off | W_attn] + [b_off | b_attn]
    tgemm_kernel<false><<<dim3(6, MB), 256>>>(p_q, p_Wpack, p_bpack, p_offattn, T, 384, 256);

    // 3. deformable sampling + softmax fused
    sample_kernel<<<T, 256>>>(rp, T);

    // 4. x2 = samp @ W_out + b_out
    tgemm_kernel<false><<<dim3(4, MB), 256>>>(p_samp, Wout, bout, p_x2, T, 256, 256);

    // 5. x = LN(src + x2)
    ln_kernel<<<(T * 32 + 255) / 256, 256>>>(src, p_x2, g1, be1, p_x, T);

    // 6. h = relu(x @ W1 + b1)
    tgemm_kernel<true><<<dim3(16, MB), 256>>>(p_x, W1, b1, p_h, T, 1024, 256);

    // 7. f = h @ W2 + b2
    tgemm_kernel<false><<<dim3(4, MB), 256>>>(p_h, W2, b2, p_f, T, 256, 1024);

    // 8. out = LN(x + f)
    ln_kernel<<<(T * 32 + 255) / 256, 256>>>(p_x, p_f, g2, be2, (float*)d_out, T);
}

// round 4
// speedup vs baseline: 2.8088x; 1.1461x over previous
#include <cuda_runtime.h>
#include <math.h>
#include <stdint.h>

#define LQ 13294
#define DMODEL 256
#define MAXN 2

// ---------------- scratch (device globals; no allocation) ----------------
__device__ float g_value[MAXN*LQ*DMODEL];      // [T,256]
__device__ float g_q[MAXN*LQ*DMODEL];          // [T,256] src+pos
__device__ float g_offattn[MAXN*LQ*384];       // [T,384]
__device__ float g_samp[MAXN*LQ*DMODEL];       // [T,256]
__device__ float g_x2[MAXN*LQ*DMODEL];         // [T,256]
__device__ float g_x[MAXN*LQ*DMODEL];          // [T,256]
__device__ float g_hbuf[MAXN*LQ*1024];         // [T,1024]
__device__ float g_fbuf[MAXN*LQ*DMODEL];       // [T,256]
__device__ float g_Wpack[256*384];
__device__ float g_bpack[384];

// ---------------- pack W_off|W_attn into one [256,384] ----------------
__global__ void pack_w_kernel(const float* __restrict__ Woff, const float* __restrict__ Wattn,
                              const float* __restrict__ boff, const float* __restrict__ battn) {
    int i = blockIdx.x * 256 + threadIdx.x;
    if (i < 256 * 384) {
        int k = i / 384, c = i - k * 384;
        g_Wpack[i] = (c < 256) ? Woff[k * 256 + c] : Wattn[k * 128 + (c - 256)];
    }
    if (i < 384) g_bpack[i] = (i < 256) ? boff[i] : battn[i - 256];
}

// ---------------- q = src + pos (float4) ----------------
__global__ void add_kernel(const float* __restrict__ a, const float* __restrict__ b,
                           float* __restrict__ o, int n4) {
    int i = blockIdx.x * blockDim.x + threadIdx.x;
    if (i < n4) {
        float4 va = ((const float4*)a)[i];
        float4 vb = ((const float4*)b)[i];
        ((float4*)o)[i] = make_float4(va.x + vb.x, va.y + vb.y, va.z + vb.z, va.w + vb.w);
    }
}

// ---------------- tf32 tensor-core GEMM, 3-stage cp.async, BM128/BN128/BK32 ----------------
// C[M,N] = A @ B + bias, optional ReLU. B is [K,N] row-major.
// 256 threads = 8 warps in 4(M) x 2(N); warp tile 32x64.

__device__ __forceinline__ void mma_tf32(float* d, const uint32_t* a, const uint32_t* b) {
    asm volatile(
        "mma.sync.aligned.m16n8k8.row.col.f32.tf32.tf32.f32 "
        "{%0,%1,%2,%3}, {%4,%5,%6,%7}, {%8,%9}, {%0,%1,%2,%3};\n"
        : "+f"(d[0]), "+f"(d[1]), "+f"(d[2]), "+f"(d[3])
        : "r"(a[0]), "r"(a[1]), "r"(a[2]), "r"(a[3]), "r"(b[0]), "r"(b[1]));
}

__device__ __forceinline__ void cp_async16(uint32_t saddr, const void* gptr, int srcbytes) {
    asm volatile("cp.async.cg.shared.global [%0], [%1], 16, %2;\n"
                 :: "r"(saddr), "l"(gptr), "r"(srcbytes));
}
__device__ __forceinline__ void cp_commit() { asm volatile("cp.async.commit_group;\n"); }
template<int N>
__device__ __forceinline__ void cp_wait() { asm volatile("cp.async.wait_group %0;\n" :: "n"(N)); }

#define ASTRIDE 36            // 128 rows; 36 % 32 == 4 -> A frag reads conflict-free
#define BSTRIDE 136           // 32 rows;  136 % 32 == 8 -> B frag reads conflict-free
#define STAGE_F (128*ASTRIDE + 32*BSTRIDE)   // floats per stage = 8960
#define B_OFF_F (128*ASTRIDE)                // 4608
#define GEMM_SMEM (3 * STAGE_F * 4)          // 107520 bytes

template<bool RELU>
__global__ void __launch_bounds__(256) tgemm_kernel(
    const float* __restrict__ A, const float* __restrict__ B,
    const float* __restrict__ bias, float* __restrict__ C,
    int M, int N, int K)
{
    extern __shared__ float smem_f[];
    const uint32_t smem_u = (uint32_t)__cvta_generic_to_shared(smem_f);

    const int tid = threadIdx.x;
    const int bm = blockIdx.y * 128;
    const int bn = blockIdx.x * 128;
    const int wid = tid >> 5;
    const int lane = tid & 31;
    const int wm = (wid & 3) * 32;
    const int wn = (wid >> 2) * 64;
    const int r = lane >> 2;
    const int c = lane & 3;

    // load geometry
    const int a_row = tid >> 1;
    const int a_cb  = (tid & 1) * 4;   // first 16B-chunk within row (of 8)
    const int b_row = tid >> 3;        // 0..31
    const int b_cb  = tid & 7;         // chunk within row: b_cb + j*8 (of 32)

    float acc[2][8][4];
    #pragma unroll
    for (int i = 0; i < 2; i++)
        #pragma unroll
        for (int j = 0; j < 8; j++)
            #pragma unroll
            for (int k = 0; k < 4; k++) acc[i][j][k] = 0.f;

    const int ktiles = K >> 5;

    auto issue_tile = [&](int kt, int s) {
        const int kk = kt * 32;
        const int gr = bm + a_row;
        const float* gpa = A + (size_t)gr * K + kk + a_cb * 4;
        const uint32_t abase = smem_u + (s * STAGE_F + a_row * ASTRIDE + a_cb * 4) * 4;
        const int asz = (gr < M) ? 16 : 0;
        #pragma unroll
        for (int j = 0; j < 4; j++)
            cp_async16(abase + j * 16, gpa + j * 4, asz);

        const float* gpb = B + (size_t)(kk + b_row) * N + bn + b_cb * 4;
        const uint32_t bbase = smem_u + (s * STAGE_F + B_OFF_F + b_row * BSTRIDE + b_cb * 4) * 4;
        #pragma unroll
        for (int j = 0; j < 4; j++)
            cp_async16(bbase + j * 8 * 16, gpb + j * 32, 16);
        cp_commit();
    };

    issue_tile(0, 0);
    if (ktiles > 1) issue_tile(1, 1);
    else cp_commit();

    for (int kt = 0; kt < ktiles; kt++) {
        const int cur = kt % 3;
        cp_wait<1>();
        __syncthreads();

        if (kt + 2 < ktiles) issue_tile(kt + 2, (kt + 2) % 3);
        else cp_commit();   // keep group FIFO accounting

        const float* As = smem_f + cur * STAGE_F;
        const float* Bs = smem_f + cur * STAGE_F + B_OFF_F;

        #pragma unroll
        for (int ks = 0; ks < 4; ks++) {
            const int k0 = ks * 8;
            uint32_t af[2][4], bf[8][2];
            #pragma unroll
            for (int mt = 0; mt < 2; mt++) {
                int rb = wm + mt * 16 + r;
                af[mt][0] = __float_as_uint(As[rb * ASTRIDE + k0 + c]);
                af[mt][1] = __float_as_uint(As[(rb + 8) * ASTRIDE + k0 + c]);
                af[mt][2] = __float_as_uint(As[rb * ASTRIDE + k0 + c + 4]);
                af[mt][3] = __float_as_uint(As[(rb + 8) * ASTRIDE + k0 + c + 4]);
            }
            #pragma unroll
            for (int nt = 0; nt < 8; nt++) {
                int cb = wn + nt * 8 + r;
                bf[nt][0] = __float_as_uint(Bs[(k0 + c) * BSTRIDE + cb]);
                bf[nt][1] = __float_as_uint(Bs[(k0 + c + 4) * BSTRIDE + cb]);
            }
            #pragma unroll
            for (int mt = 0; mt < 2; mt++)
                #pragma unroll
                for (int nt = 0; nt < 8; nt++)
                    mma_tf32(acc[mt][nt], af[mt], bf[nt]);
        }
        __syncthreads();
    }

    // ---- epilogue ----
    #pragma unroll
    for (int mt = 0; mt < 2; mt++) {
        #pragma unroll
        for (int nt = 0; nt < 8; nt++) {
            int col = bn + wn + nt * 8 + 2 * c;
            float b0 = __ldg(bias + col), b1 = __ldg(bias + col + 1);
            int row0 = bm + wm + mt * 16 + r;
            if (row0 < M) {
                float v0 = acc[mt][nt][0] + b0;
                float v1 = acc[mt][nt][1] + b1;
                if (RELU) { v0 = fmaxf(v0, 0.f); v1 = fmaxf(v1, 0.f); }
                *(float2*)(C + (size_t)row0 * N + col) = make_float2(v0, v1);
            }
            int row1 = row0 + 8;
            if (row1 < M) {
                float v2 = acc[mt][nt][2] + b0;
                float v3 = acc[mt][nt][3] + b1;
                if (RELU) { v2 = fmaxf(v2, 0.f); v3 = fmaxf(v3, 0.f); }
                *(float2*)(C + (size_t)row1 * N + col) = make_float2(v2, v3);
            }
        }
    }
}

// ---------------- deformable sampling: one warp per (token, head) ----------------
__global__ void __launch_bounds__(256) sample_kernel(const float* __restrict__ rp, int T)
{
    const int t = blockIdx.x;
    if (t >= T) return;
    const int h = threadIdx.x >> 5;
    const int lane = threadIdx.x & 31;
    const unsigned FULL = 0xffffffffu;

    const float* raw = g_offattn + (size_t)t * 384;
    float offv = raw[h * 32 + lane];
    float av = (lane < 16) ? raw[256 + h * 16 + lane] : -1e30f;
    float m = av;
    #pragma unroll
    for (int o = 16; o; o >>= 1) m = fmaxf(m, __shfl_xor_sync(FULL, m, o));
    float e = (lane < 16) ? __expf(av - m) : 0.f;
    float s = e;
    #pragma unroll
    for (int o = 16; o; o >>= 1) s += __shfl_xor_sync(FULL, s, o);
    const float anorm = e / s;

    float refv = (lane < 8) ? rp[(size_t)t * 8 + lane] : 0.f;

    const int LSa[4] = {0, 10000, 12500, 13125};
    const int Wla[4] = {100, 50, 25, 13};

    const int p = lane;
    const int l = (p >> 2) & 3;
    const int Wi = Wla[l];
    float rx = __shfl_sync(FULL, refv, 2 * l);
    float ry = __shfl_sync(FULL, refv, 2 * l + 1);
    float ox = __shfl_sync(FULL, offv, (2 * p) & 31);
    float oy = __shfl_sync(FULL, offv, (2 * p + 1) & 31);

    float x = rx * (float)Wi + ox - 0.5f;
    float y = ry * (float)Wi + oy - 0.5f;   // H == W for all levels
    float xf = floorf(x), yf = floorf(y);
    int x0 = (int)xf, y0 = (int)yf;
    float wx1 = x - xf, wy1 = y - yf;
    float wx0 = 1.f - wx1, wy0 = 1.f - wy1;

    int   idxs[4];
    float ws[4];
    #pragma unroll
    for (int tap = 0; tap < 4; tap++) {
        int dx = tap & 1, dy = tap >> 1;
        int xi = x0 + dx, yi = y0 + dy;
        bool valid = (xi >= 0) & (xi < Wi) & (yi >= 0) & (yi < Wi);
        float w = (dx ? wx1 : wx0) * (dy ? wy1 : wy0) * anorm;
        int xic = min(max(xi, 0), Wi - 1);
        int yic = min(max(yi, 0), Wi - 1);
        idxs[tap] = LSa[l] + yic * Wi + xic;
        ws[tap] = valid ? w : 0.f;
    }

    const int n = (t >= LQ) ? 1 : 0;
    const float* vbase = g_value + ((size_t)n * LQ) * 256 + h * 32 + lane;

    float acc0 = 0.f, acc1 = 0.f, acc2 = 0.f, acc3 = 0.f;
    #pragma unroll
    for (int q = 0; q < 16; q++) {
        int i0 = __shfl_sync(FULL, idxs[0], q);
        int i1 = __shfl_sync(FULL, idxs[1], q);
        int i2 = __shfl_sync(FULL, idxs[2], q);
        int i3 = __shfl_sync(FULL, idxs[3], q);
        float w0 = __shfl_sync(FULL, ws[0], q);
        float w1 = __shfl_sync(FULL, ws[1], q);
        float w2 = __shfl_sync(FULL, ws[2], q);
        float w3 = __shfl_sync(FULL, ws[3], q);
        float v0 = __ldg(vbase + (size_t)i0 * 256);
        float v1 = __ldg(vbase + (size_t)i1 * 256);
        float v2 = __ldg(vbase + (size_t)i2 * 256);
        float v3 = __ldg(vbase + (size_t)i3 * 256);
        acc0 = fmaf(w0, v0, acc0);
        acc1 = fmaf(w1, v1, acc1);
        acc2 = fmaf(w2, v2, acc2);
        acc3 = fmaf(w3, v3, acc3);
    }
    g_samp[(size_t)t * 256 + h * 32 + lane] = (acc0 + acc1) + (acc2 + acc3);
}

// ---------------- LayerNorm: one warp per token, out = LN(a+b)*g + be ----------------
__global__ void __launch_bounds__(256) ln_kernel(
    const float* __restrict__ a, const float* __restrict__ b,
    const float* __restrict__ g, const float* __restrict__ be,
    float* __restrict__ out, int T)
{
    const int warp = (blockIdx.x * blockDim.x + threadIdx.x) >> 5;
    if (warp >= T) return;
    const int lane = threadIdx.x & 31;
    const size_t base = (size_t)warp * 256 + lane * 8;

    float4 a0 = *(const float4*)(a + base);
    float4 a1 = *(const float4*)(a + base + 4);
    float4 b0 = *(const float4*)(b + base);
    float4 b1 = *(const float4*)(b + base + 4);
    float v[8] = {a0.x + b0.x, a0.y + b0.y, a0.z + b0.z, a0.w + b0.w,
                  a1.x + b1.x, a1.y + b1.y, a1.z + b1.z, a1.w + b1.w};
    float s = 0.f, s2 = 0.f;
    #pragma unroll
    for (int i = 0; i < 8; i++) { s += v[i]; s2 = fmaf(v[i], v[i], s2); }
    #pragma unroll
    for (int o = 16; o; o >>= 1) {
        s  += __shfl_xor_sync(0xffffffffu, s,  o);
        s2 += __shfl_xor_sync(0xffffffffu, s2, o);
    }
    float mu = s * (1.f / 256.f);
    float var = s2 * (1.f / 256.f) - mu * mu;
    float rstd = rsqrtf(var + 1e-5f);

    float4 gg0 = *(const float4*)(g + lane * 8);
    float4 gg1 = *(const float4*)(g + lane * 8 + 4);
    float4 bb0 = *(const float4*)(be + lane * 8);
    float4 bb1 = *(const float4*)(be + lane * 8 + 4);
    float gv[8] = {gg0.x, gg0.y, gg0.z, gg0.w, gg1.x, gg1.y, gg1.z, gg1.w};
    float bv[8] = {bb0.x, bb0.y, bb0.z, bb0.w, bb1.x, bb1.y, bb1.z, bb1.w};
    float o0[8];
    #pragma unroll
    for (int i = 0; i < 8; i++) o0[i] = (v[i] - mu) * rstd * gv[i] + bv[i];
    *(float4*)(out + base)     = make_float4(o0[0], o0[1], o0[2], o0[3]);
    *(float4*)(out + base + 4) = make_float4(o0[4], o0[5], o0[6], o0[7]);
}

// ---------------- host launcher ----------------
extern "C" void kernel_launch(void* const* d_in, const int* in_sizes, int n_in,
                              void* d_out, int out_size)
{
    const float* src   = (const float*)d_in[0];
    const float* pos   = (const float*)d_in[1];
    const float* rp    = (const float*)d_in[2];
    const float* Wv    = (const float*)d_in[5];
    const float* bv    = (const float*)d_in[6];
    const float* Woff  = (const float*)d_in[7];
    const float* boff  = (const float*)d_in[8];
    const float* Wattn = (const float*)d_in[9];
    const float* battn = (const float*)d_in[10];
    const float* Wout  = (const float*)d_in[11];
    const float* bout  = (const float*)d_in[12];
    const float* W1    = (const float*)d_in[13];
    const float* b1    = (const float*)d_in[14];
    const float* W2    = (const float*)d_in[15];
    const float* b2    = (const float*)d_in[16];
    const float* g1    = (const float*)d_in[17];
    const float* be1   = (const float*)d_in[18];
    const float* g2    = (const float*)d_in[19];
    const float* be2   = (const float*)d_in[20];

    const int T = in_sizes[0] / DMODEL;   // N * Lq

    float *p_value, *p_q, *p_offattn, *p_samp, *p_x2, *p_x, *p_h, *p_f, *p_Wpack, *p_bpack;
    cudaGetSymbolAddress((void**)&p_value,   g_value);
    cudaGetSymbolAddress((void**)&p_q,       g_q);
    cudaGetSymbolAddress((void**)&p_offattn, g_offattn);
    cudaGetSymbolAddress((void**)&p_samp,    g_samp);
    cudaGetSymbolAddress((void**)&p_x2,      g_x2);
    cudaGetSymbolAddress((void**)&p_x,       g_x);
    cudaGetSymbolAddress((void**)&p_h,       g_hbuf);
    cudaGetSymbolAddress((void**)&p_f,       g_fbuf);
    cudaGetSymbolAddress((void**)&p_Wpack,   g_Wpack);
    cudaGetSymbolAddress((void**)&p_bpack,   g_bpack);

    static bool attr_done = false;
    if (!attr_done) {
        cudaFuncSetAttribute(tgemm_kernel<false>, cudaFuncAttributeMaxDynamicSharedMemorySize, GEMM_SMEM);
        cudaFuncSetAttribute(tgemm_kernel<true>,  cudaFuncAttributeMaxDynamicSharedMemorySize, GEMM_SMEM);
        attr_done = true;
    }

    const int MB = (T + 127) / 128;
    const int n4 = T * DMODEL / 4;

    pack_w_kernel<<<384, 256>>>(Woff, Wattn, boff, battn);
    add_kernel<<<(n4 + 255) / 256, 256>>>(src, pos, p_q, n4);

    // 1. value = src @ Wv + bv
    tgemm_kernel<false><<<dim3(2, MB), 256, GEMM_SMEM>>>(src, Wv, bv, p_value, T, 256, 256);

    // 2. offattn = q @ [W_off | W_attn] + [b_off | b_attn]
    tgemm_kernel<false><<<dim3(3, MB), 256, GEMM_SMEM>>>(p_q, p_Wpack, p_bpack, p_offattn, T, 384, 256);

    // 3. deformable sampling + softmax fused
    sample_kernel<<<T, 256>>>(rp, T);

    // 4. x2 = samp @ W_out + b_out
    tgemm_kernel<false><<<dim3(2, MB), 256, GEMM_SMEM>>>(p_samp, Wout, bout, p_x2, T, 256, 256);

    // 5. x = LN(src + x2)
    ln_kernel<<<(T * 32 + 255) / 256, 256>>>(src, p_x2, g1, be1, p_x, T);

    // 6. h = relu(x @ W1 + b1)
    tgemm_kernel<true><<<dim3(8, MB), 256, GEMM_SMEM>>>(p_x, W1, b1, p_h, T, 1024, 256);

    // 7. f = h @ W2 + b2
    tgemm_kernel<false><<<dim3(2, MB), 256, GEMM_SMEM>>>(p_h, W2, b2, p_f, T, 256, 1024);

    // 8. out = LN(x + f)
    ln_kernel<<<(T * 32 + 255) / 256, 256>>>(p_x, p_f, g2, be2, (float*)d_out, T);
}

// round 6
// speedup vs baseline: 3.6346x; 1.2940x over previous
#include <cuda_runtime.h>
#include <cuda_fp16.h>
#include <math.h>
#include <stdint.h>

#define LQ 13294
#define DMODEL 256
#define MAXN 2

// ---------------- scratch (device globals; no allocation) ----------------
__device__ float  g_value[MAXN*LQ*DMODEL];     // [T,256] f32 (sampling source)
__device__ float  g_offattn[MAXN*LQ*384];      // [T,384] f32
__device__ float  g_x[MAXN*LQ*DMODEL];         // [T,256] f32 (residual)
__device__ float  g_x2[MAXN*LQ*DMODEL];        // [T,256] f32
__device__ float  g_fbuf[MAXN*LQ*DMODEL];      // [T,256] f32
__device__ __half g_src_h[MAXN*LQ*DMODEL];     // half GEMM inputs
__device__ __half g_q_h[MAXN*LQ*DMODEL];
__device__ __half g_samp_h[MAXN*LQ*DMODEL];
__device__ __half g_x_h[MAXN*LQ*DMODEL];
__device__ __half g_h_h[MAXN*LQ*1024];         // FFN intermediate, half only
// transposed half weights [N][K]
__device__ __half g_Wvt[256*256];
__device__ __half g_Wpackt[384*256];
__device__ __half g_Woutt[256*256];
__device__ __half g_W1t[1024*256];
__device__ __half g_W2t[256*1024];
__device__ float  g_bpack[384];

// ---------------- small prep kernels ----------------
__global__ void pack_b_kernel(const float* __restrict__ boff, const float* __restrict__ battn) {
    int i = blockIdx.x * 128 + threadIdx.x;
    if (i < 384) g_bpack[i] = (i < 256) ? boff[i] : battn[i - 256];
}

__global__ void cvt_kernel(const float* __restrict__ in, __half* __restrict__ out, int n4) {
    int i = blockIdx.x * blockDim.x + threadIdx.x;
    if (i < n4) {
        float4 v = ((const float4*)in)[i];
        __half2* o = (__half2*)out;
        o[2 * i]     = __floats2half2_rn(v.x, v.y);
        o[2 * i + 1] = __floats2half2_rn(v.z, v.w);
    }
}

__global__ void add_h_kernel(const float* __restrict__ a, const float* __restrict__ b,
                             __half* __restrict__ o, int n4) {
    int i = blockIdx.x * blockDim.x + threadIdx.x;
    if (i < n4) {
        float4 va = ((const float4*)a)[i];
        float4 vb = ((const float4*)b)[i];
        __half2* oo = (__half2*)o;
        oo[2 * i]     = __floats2half2_rn(va.x + vb.x, va.y + vb.y);
        oo[2 * i + 1] = __floats2half2_rn(va.z + vb.z, va.w + vb.w);
    }
}

// transpose in[R][C] f32 -> out[C][R] half
__global__ void transpose_h_kernel(const float* __restrict__ in, __half* __restrict__ out,
                                   int R, int C) {
    __shared__ float tile[32][33];
    int bx = blockIdx.x * 32;
    int by = blockIdx.y * 32;
    int x = bx + threadIdx.x;
    #pragma unroll
    for (int i = 0; i < 4; i++) {
        int y = by + threadIdx.y + i * 8;
        if (y < R && x < C) tile[threadIdx.y + i * 8][threadIdx.x] = in[(size_t)y * C + x];
    }
    __syncthreads();
    int xo = by + threadIdx.x;
    #pragma unroll
    for (int i = 0; i < 4; i++) {
        int yo = bx + threadIdx.y + i * 8;
        if (yo < C && xo < R) out[(size_t)yo * R + xo] = __float2half(tile[threadIdx.x][threadIdx.y + i * 8]);
    }
}

// ---------------- fp16 tensor-core GEMM (m16n8k16, fp32 accum) ----------------
// C[M,N] = A[M,K] @ Bt[N,K]^T + bias. A, Bt half; C f32 (or half).
// BM=128, BN=128, BK=32, 256 threads = 8 warps (4M x 2N), warp tile 32x64.
// 3-stage cp.async ring, one __syncthreads per k-tile.

__device__ __forceinline__ void mma_f16(float* d, const uint32_t* a, const uint32_t* b) {
    asm volatile(
        "mma.sync.aligned.m16n8k16.row.col.f32.f16.f16.f32 "
        "{%0,%1,%2,%3}, {%4,%5,%6,%7}, {%8,%9}, {%0,%1,%2,%3};\n"
        : "+f"(d[0]), "+f"(d[1]), "+f"(d[2]), "+f"(d[3])
        : "r"(a[0]), "r"(a[1]), "r"(a[2]), "r"(a[3]), "r"(b[0]), "r"(b[1]));
}

__device__ __forceinline__ void cp_async16(uint32_t saddr, const void* gptr, int srcbytes) {
    asm volatile("cp.async.cg.shared.global [%0], [%1], 16, %2;\n"
                 :: "r"(saddr), "l"(gptr), "r"(srcbytes));
}
__device__ __forceinline__ void cp_commit() { asm volatile("cp.async.commit_group;\n"); }
template<int N>
__device__ __forceinline__ void cp_wait() { asm volatile("cp.async.wait_group %0;\n" :: "n"(N)); }

#define HSTRIDE 40                          // halves per row (80B, 16B-aligned, conflict-free)
#define TILE_H (128*HSTRIDE)                // halves per tile = 5120
#define STAGE_BYTES (2*TILE_H*2)            // A+B per stage = 20480 B
#define GEMM_DSMEM (3*STAGE_BYTES)          // 61440 B

template<bool RELU, bool HALF_OUT>
__global__ void __launch_bounds__(256) hgemm_kernel(
    const __half* __restrict__ A, const __half* __restrict__ Bt,
    const float* __restrict__ bias, void* __restrict__ Cv,
    int M, int N, int K)
{
    extern __shared__ __align__(16) char smem_raw[];
    const uint32_t smem_u = (uint32_t)__cvta_generic_to_shared(smem_raw);

    const int tid = threadIdx.x;
    const int wid = tid >> 5;
    const int lane = tid & 31;
    const int bm = blockIdx.y * 128;
    const int bn = blockIdx.x * 128;
    const int wm = (wid & 3) * 32;
    const int wn = (wid >> 2) * 64;
    const int r = lane >> 2;
    const int c = lane & 3;

    // load geometry: A chunks idx in [0,512): row=idx>>2, ch=idx&3 (8 halves per chunk)
    const int i_row0 = tid >> 2, i_ch0 = tid & 3;          // idx = tid
    const int i_row1 = (tid + 256) >> 2, i_ch1 = tid & 3;  // idx = tid+256

    float acc[2][8][4];
    #pragma unroll
    for (int i = 0; i < 2; i++)
        #pragma unroll
        for (int j = 0; j < 8; j++)
            #pragma unroll
            for (int k = 0; k < 4; k++) acc[i][j][k] = 0.f;

    const int ktiles = K >> 5;

    auto issue_tile = [&](int kt, int s) {
        const int kk = kt * 32;
        const uint32_t sb = smem_u + s * STAGE_BYTES;
        // A
        {
            int gr = bm + i_row0;
            cp_async16(sb + (i_row0 * HSTRIDE + i_ch0 * 8) * 2,
                       A + (size_t)gr * K + kk + i_ch0 * 8, (gr < M) ? 16 : 0);
            gr = bm + i_row1;
            cp_async16(sb + (i_row1 * HSTRIDE + i_ch1 * 8) * 2,
                       A + (size_t)gr * K + kk + i_ch1 * 8, (gr < M) ? 16 : 0);
        }
        // B
        {
            const uint32_t bb = sb + TILE_H * 2;
            cp_async16(bb + (i_row0 * HSTRIDE + i_ch0 * 8) * 2,
                       Bt + (size_t)(bn + i_row0) * K + kk + i_ch0 * 8, 16);
            cp_async16(bb + (i_row1 * HSTRIDE + i_ch1 * 8) * 2,
                       Bt + (size_t)(bn + i_row1) * K + kk + i_ch1 * 8, 16);
        }
        cp_commit();
    };

    issue_tile(0, 0);
    if (ktiles > 1) issue_tile(1, 1); else cp_commit();

    for (int kt = 0; kt < ktiles; kt++) {
        const int cur = kt % 3;
        cp_wait<1>();
        __syncthreads();   // stage cur ready for all; stage (kt+2)%3 dead (compute kt-1 done)

        if (kt + 2 < ktiles) issue_tile(kt + 2, (kt + 2) % 3);
        else cp_commit();

        const __half* As = (const __half*)(smem_raw + cur * STAGE_BYTES);
        const __half* Bs = As + TILE_H;

        #pragma unroll
        for (int ks = 0; ks < 2; ks++) {
            const int k0 = ks * 16 + c * 2;
            uint32_t af[2][4], bf[8][2];
            #pragma unroll
            for (int mt = 0; mt < 2; mt++) {
                const __half* ar = As + (wm + mt * 16 + r) * HSTRIDE + k0;
                af[mt][0] = *(const uint32_t*)(ar);
                af[mt][1] = *(const uint32_t*)(ar + 8 * HSTRIDE);
                af[mt][2] = *(const uint32_t*)(ar + 8);
                af[mt][3] = *(const uint32_t*)(ar + 8 * HSTRIDE + 8);
            }
            #pragma unroll
            for (int nt = 0; nt < 8; nt++) {
                const __half* br = Bs + (wn + nt * 8 + r) * HSTRIDE + k0;
                bf[nt][0] = *(const uint32_t*)(br);
                bf[nt][1] = *(const uint32_t*)(br + 8);
            }
            #pragma unroll
            for (int mt = 0; mt < 2; mt++)
                #pragma unroll
                for (int nt = 0; nt < 8; nt++)
                    mma_f16(acc[mt][nt], af[mt], bf[nt]);
        }
        __syncthreads();
    }

    // ---- epilogue ----
    #pragma unroll
    for (int mt = 0; mt < 2; mt++) {
        #pragma unroll
        for (int nt = 0; nt < 8; nt++) {
            int col = bn + wn + nt * 8 + 2 * c;
            float b0 = __ldg(bias + col), b1 = __ldg(bias + col + 1);
            int row0 = bm + wm + mt * 16 + r;
            int row1 = row0 + 8;
            float v0 = acc[mt][nt][0] + b0, v1 = acc[mt][nt][1] + b1;
            float v2 = acc[mt][nt][2] + b0, v3 = acc[mt][nt][3] + b1;
            if (RELU) {
                v0 = fmaxf(v0, 0.f); v1 = fmaxf(v1, 0.f);
                v2 = fmaxf(v2, 0.f); v3 = fmaxf(v3, 0.f);
            }
            if (HALF_OUT) {
                __half* Ch = (__half*)Cv;
                if (row0 < M) *(__half2*)(Ch + (size_t)row0 * N + col) = __floats2half2_rn(v0, v1);
                if (row1 < M) *(__half2*)(Ch + (size_t)row1 * N + col) = __floats2half2_rn(v2, v3);
            } else {
                float* Cf = (float*)Cv;
                if (row0 < M) *(float2*)(Cf + (size_t)row0 * N + col) = make_float2(v0, v1);
                if (row1 < M) *(float2*)(Cf + (size_t)row1 * N + col) = make_float2(v2, v3);
            }
        }
    }
}

// ---------------- deformable sampling: one warp per (token, head) ----------------
__global__ void __launch_bounds__(256) sample_kernel(const float* __restrict__ rp, int T)
{
    const int t = blockIdx.x;
    if (t >= T) return;
    const int h = threadIdx.x >> 5;
    const int lane = threadIdx.x & 31;
    const unsigned FULL = 0xffffffffu;

    const float* raw = g_offattn + (size_t)t * 384;
    float offv = raw[h * 32 + lane];
    float av = (lane < 16) ? raw[256 + h * 16 + lane] : -1e30f;
    float m = av;
    #pragma unroll
    for (int o = 16; o; o >>= 1) m = fmaxf(m, __shfl_xor_sync(FULL, m, o));
    float e = (lane < 16) ? __expf(av - m) : 0.f;
    float s = e;
    #pragma unroll
    for (int o = 16; o; o >>= 1) s += __shfl_xor_sync(FULL, s, o);
    const float anorm = e / s;

    float refv = (lane < 8) ? rp[(size_t)t * 8 + lane] : 0.f;

    const int LSa[4] = {0, 10000, 12500, 13125};
    const int Wla[4] = {100, 50, 25, 13};

    const int p = lane;
    const int l = (p >> 2) & 3;
    const int Wi = Wla[l];
    float rx = __shfl_sync(FULL, refv, 2 * l);
    float ry = __shfl_sync(FULL, refv, 2 * l + 1);
    float ox = __shfl_sync(FULL, offv, (2 * p) & 31);
    float oy = __shfl_sync(FULL, offv, (2 * p + 1) & 31);

    float x = rx * (float)Wi + ox - 0.5f;
    float y = ry * (float)Wi + oy - 0.5f;   // H == W for all levels
    float xf = floorf(x), yf = floorf(y);
    int x0 = (int)xf, y0 = (int)yf;
    float wx1 = x - xf, wy1 = y - yf;
    float wx0 = 1.f - wx1, wy0 = 1.f - wy1;

    int   idxs[4];
    float ws[4];
    #pragma unroll
    for (int tap = 0; tap < 4; tap++) {
        int dx = tap & 1, dy = tap >> 1;
        int xi = x0 + dx, yi = y0 + dy;
        bool valid = (xi >= 0) & (xi < Wi) & (yi >= 0) & (yi < Wi);
        float w = (dx ? wx1 : wx0) * (dy ? wy1 : wy0) * anorm;
        int xic = min(max(xi, 0), Wi - 1);
        int yic = min(max(yi, 0), Wi - 1);
        idxs[tap] = LSa[l] + yic * Wi + xic;
        ws[tap] = valid ? w : 0.f;
    }

    const int n = (t >= LQ) ? 1 : 0;
    const float* vbase = g_value + ((size_t)n * LQ) * 256 + h * 32 + lane;

    float acc0 = 0.f, acc1 = 0.f, acc2 = 0.f, acc3 = 0.f;
    #pragma unroll
    for (int q = 0; q < 16; q++) {
        int i0 = __shfl_sync(FULL, idxs[0], q);
        int i1 = __shfl_sync(FULL, idxs[1], q);
        int i2 = __shfl_sync(FULL, idxs[2], q);
        int i3 = __shfl_sync(FULL, idxs[3], q);
        float w0 = __shfl_sync(FULL, ws[0], q);
        float w1 = __shfl_sync(FULL, ws[1], q);
        float w2 = __shfl_sync(FULL, ws[2], q);
        float w3 = __shfl_sync(FULL, ws[3], q);
        float v0 = __ldg(vbase + (size_t)i0 * 256);
        float v1 = __ldg(vbase + (size_t)i1 * 256);
        float v2 = __ldg(vbase + (size_t)i2 * 256);
        float v3 = __ldg(vbase + (size_t)i3 * 256);
        acc0 = fmaf(w0, v0, acc0);
        acc1 = fmaf(w1, v1, acc1);
        acc2 = fmaf(w2, v2, acc2);
        acc3 = fmaf(w3, v3, acc3);
    }
    g_samp_h[(size_t)t * 256 + h * 32 + lane] = __float2half((acc0 + acc1) + (acc2 + acc3));
}

// ---------------- LayerNorm: one warp per token, out = LN(a+b)*g + be ----------------
template<bool WRITEH>
__global__ void __launch_bounds__(256) ln_kernel(
    const float* __restrict__ a, const float* __restrict__ b,
    const float* __restrict__ g, const float* __restrict__ be,
    float* __restrict__ out, __half* __restrict__ outh, int T)
{
    const int warp = (blockIdx.x * blockDim.x + threadIdx.x) >> 5;
    if (warp >= T) return;
    const int lane = threadIdx.x & 31;
    const size_t base = (size_t)warp * 256 + lane * 8;

    float4 a0 = *(const float4*)(a + base);
    float4 a1 = *(const float4*)(a + base + 4);
    float4 b0 = *(const float4*)(b + base);
    float4 b1 = *(const float4*)(b + base + 4);
    float v[8] = {a0.x + b0.x, a0.y + b0.y, a0.z + b0.z, a0.w + b0.w,
                  a1.x + b1.x, a1.y + b1.y, a1.z + b1.z, a1.w + b1.w};
    float s = 0.f, s2 = 0.f;
    #pragma unroll
    for (int i = 0; i < 8; i++) { s += v[i]; s2 = fmaf(v[i], v[i], s2); }
    #pragma unroll
    for (int o = 16; o; o >>= 1) {
        s  += __shfl_xor_sync(0xffffffffu, s,  o);
        s2 += __shfl_xor_sync(0xffffffffu, s2, o);
    }
    float mu = s * (1.f / 256.f);
    float var = s2 * (1.f / 256.f) - mu * mu;
    float rstd = rsqrtf(var + 1e-5f);

    float4 gg0 = *(const float4*)(g + lane * 8);
    float4 gg1 = *(const float4*)(g + lane * 8 + 4);
    float4 bb0 = *(const float4*)(be + lane * 8);
    float4 bb1 = *(const float4*)(be + lane * 8 + 4);
    float gv[8] = {gg0.x, gg0.y, gg0.z, gg0.w, gg1.x, gg1.y, gg1.z, gg1.w};
    float bv[8] = {bb0.x, bb0.y, bb0.z, bb0.w, bb1.x, bb1.y, bb1.z, bb1.w};
    float o0[8];
    #pragma unroll
    for (int i = 0; i < 8; i++) o0[i] = (v[i] - mu) * rstd * gv[i] + bv[i];
    *(float4*)(out + base)     = make_float4(o0[0], o0[1], o0[2], o0[3]);
    *(float4*)(out + base + 4) = make_float4(o0[4], o0[5], o0[6], o0[7]);
    if (WRITEH) {
        __half2* oh = (__half2*)(outh + base);
        oh[0] = __floats2half2_rn(o0[0], o0[1]);
        oh[1] = __floats2half2_rn(o0[2], o0[3]);
        oh[2] = __floats2half2_rn(o0[4], o0[5]);
        oh[3] = __floats2half2_rn(o0[6], o0[7]);
    }
}

// ---------------- host launcher ----------------
extern "C" void kernel_launch(void* const* d_in, const int* in_sizes, int n_in,
                              void* d_out, int out_size)
{
    const float* src   = (const float*)d_in[0];
    const float* pos   = (const float*)d_in[1];
    const float* rp    = (const float*)d_in[2];
    const float* Wv    = (const float*)d_in[5];
    const float* bv    = (const float*)d_in[6];
    const float* Woff  = (const float*)d_in[7];
    const float* boff  = (const float*)d_in[8];
    const float* Wattn = (const float*)d_in[9];
    const float* battn = (const float*)d_in[10];
    const float* Wout  = (const float*)d_in[11];
    const float* bout  = (const float*)d_in[12];
    const float* W1    = (const float*)d_in[13];
    const float* b1    = (const float*)d_in[14];
    const float* W2    = (const float*)d_in[15];
    const float* b2    = (const float*)d_in[16];
    const float* g1    = (const float*)d_in[17];
    const float* be1   = (const float*)d_in[18];
    const float* g2    = (const float*)d_in[19];
    const float* be2   = (const float*)d_in[20];

    const int T = in_sizes[0] / DMODEL;   // N * Lq

    float  *p_value, *p_offattn, *p_x, *p_x2, *p_f, *p_bpack;
    __half *p_src_h, *p_q_h, *p_samp_h, *p_x_h, *p_h_h;
    __half *p_Wvt, *p_Wpackt, *p_Woutt, *p_W1t, *p_W2t;
    cudaGetSymbolAddress((void**)&p_value,   g_value);
    cudaGetSymbolAddress((void**)&p_offattn, g_offattn);
    cudaGetSymbolAddress((void**)&p_x,       g_x);
    cudaGetSymbolAddress((void**)&p_x2,      g_x2);
    cudaGetSymbolAddress((void**)&p_f,       g_fbuf);
    cudaGetSymbolAddress((void**)&p_bpack,   g_bpack);
    cudaGetSymbolAddress((void**)&p_src_h,   g_src_h);
    cudaGetSymbolAddress((void**)&p_q_h,     g_q_h);
    cudaGetSymbolAddress((void**)&p_samp_h,  g_samp_h);
    cudaGetSymbolAddress((void**)&p_x_h,     g_x_h);
    cudaGetSymbolAddress((void**)&p_h_h,     g_h_h);
    cudaGetSymbolAddress((void**)&p_Wvt,     g_Wvt);
    cudaGetSymbolAddress((void**)&p_Wpackt,  g_Wpackt);
    cudaGetSymbolAddress((void**)&p_Woutt,   g_Woutt);
    cudaGetSymbolAddress((void**)&p_W1t,     g_W1t);
    cudaGetSymbolAddress((void**)&p_W2t,     g_W2t);

    cudaFuncSetAttribute(hgemm_kernel<false, false>, cudaFuncAttributeMaxDynamicSharedMemorySize, GEMM_DSMEM);
    cudaFuncSetAttribute(hgemm_kernel<true,  true>,  cudaFuncAttributeMaxDynamicSharedMemorySize, GEMM_DSMEM);

    const int MB = (T + 127) / 128;
    const int n4 = T * DMODEL / 4;
    dim3 tb(32, 8);

    // ---- prep: transposed half weights + packed bias + half activations ----
    transpose_h_kernel<<<dim3(8, 8),  tb>>>(Wv,    p_Wvt,            256, 256);
    transpose_h_kernel<<<dim3(8, 8),  tb>>>(Woff,  p_Wpackt,         256, 256);
    transpose_h_kernel<<<dim3(4, 8),  tb>>>(Wattn, p_Wpackt + 65536, 256, 128);
    transpose_h_kernel<<<dim3(8, 8),  tb>>>(Wout,  p_Woutt,          256, 256);
    transpose_h_kernel<<<dim3(32, 8), tb>>>(W1,    p_W1t,            256, 1024);
    transpose_h_kernel<<<dim3(8, 32), tb>>>(W2,    p_W2t,            1024, 256);
    pack_b_kernel<<<3, 128>>>(boff, battn);
    cvt_kernel<<<(n4 + 255) / 256, 256>>>(src, p_src_h, n4);
    add_h_kernel<<<(n4 + 255) / 256, 256>>>(src, pos, p_q_h, n4);

    // 1. value = src @ Wv + bv            (f32 out, sampling source)
    hgemm_kernel<false, false><<<dim3(2, MB), 256, GEMM_DSMEM>>>(p_src_h, p_Wvt, bv, p_value, T, 256, 256);

    // 2. offattn = q @ [W_off|W_attn] + b (f32 out)
    hgemm_kernel<false, false><<<dim3(3, MB), 256, GEMM_DSMEM>>>(p_q_h, p_Wpackt, p_bpack, p_offattn, T, 384, 256);

    // 3. deformable sampling + softmax fused (half out)
    sample_kernel<<<T, 256>>>(rp, T);

    // 4. x2 = samp @ W_out + b_out        (f32 out)
    hgemm_kernel<false, false><<<dim3(2, MB), 256, GEMM_DSMEM>>>(p_samp_h, p_Woutt, bout, p_x2, T, 256, 256);

    // 5. x = LN(src + x2)                 (f32 + half)
    ln_kernel<true><<<(T * 32 + 255) / 256, 256>>>(src, p_x2, g1, be1, p_x, p_x_h, T);

    // 6. h = relu(x @ W1 + b1)            (half out only)
    hgemm_kernel<true, true><<<dim3(8, MB), 256, GEMM_DSMEM>>>(p_x_h, p_W1t, b1, p_h_h, T, 1024, 256);

    // 7. f = h @ W2 + b2                  (f32 out)
    hgemm_kernel<false, false><<<dim3(2, MB), 256, GEMM_DSMEM>>>(p_h_h, p_W2t, b2, p_f, T, 256, 1024);

    // 8. out = LN(x + f)
    ln_kernel<false><<<(T * 32 + 255) / 256, 256>>>(p_x, p_f, g2, be2, (float*)d_out, nullptr, T);
}

// round 7
// speedup vs baseline: 3.7156x; 1.0223x over previous
#include <cuda_runtime.h>
#include <cuda_fp16.h>
#include <math.h>
#include <stdint.h>

#define LQ 13294
#define DMODEL 256
#define MAXN 2

// ---------------- scratch (device globals; no allocation) ----------------
__device__ float  g_offattn[MAXN*LQ*384];      // [T,384] f32
__device__ float  g_x[MAXN*LQ*DMODEL];         // [T,256] f32 (residual)
__device__ float  g_x2[MAXN*LQ*DMODEL];        // [T,256] f32
__device__ float  g_fbuf[MAXN*LQ*DMODEL];      // [T,256] f32
__device__ __half g_value_h[MAXN*LQ*DMODEL];   // [T,256] half (sampling source)
__device__ __half g_src_h[MAXN*LQ*DMODEL];     // half GEMM inputs
__device__ __half g_q_h[MAXN*LQ*DMODEL];
__device__ __half g_samp_h[MAXN*LQ*DMODEL];
__device__ __half g_x_h[MAXN*LQ*DMODEL];
__device__ __half g_h_h[MAXN*LQ*1024];         // FFN intermediate, half only
// transposed half weights [N][K]
__device__ __half g_Wvt[256*256];
__device__ __half g_Wpackt[384*256];
__device__ __half g_Woutt[256*256];
__device__ __half g_W1t[1024*256];
__device__ __half g_W2t[256*1024];
__device__ float  g_bpack[384];

// ---------------- small prep kernels ----------------
__global__ void pack_b_kernel(const float* __restrict__ boff, const float* __restrict__ battn) {
    int i = blockIdx.x * 128 + threadIdx.x;
    if (i < 384) g_bpack[i] = (i < 256) ? boff[i] : battn[i - 256];
}

// src_h = half(src); q_h = half(src + pos)  (single pass over src)
__global__ void prep_act_kernel(const float* __restrict__ src, const float* __restrict__ pos,
                                int n4) {
    int i = blockIdx.x * blockDim.x + threadIdx.x;
    if (i < n4) {
        float4 vs = ((const float4*)src)[i];
        float4 vp = ((const float4*)pos)[i];
        __half2* os = (__half2*)g_src_h;
        __half2* oq = (__half2*)g_q_h;
        os[2 * i]     = __floats2half2_rn(vs.x, vs.y);
        os[2 * i + 1] = __floats2half2_rn(vs.z, vs.w);
        oq[2 * i]     = __floats2half2_rn(vs.x + vp.x, vs.y + vp.y);
        oq[2 * i + 1] = __floats2half2_rn(vs.z + vp.z, vs.w + vp.w);
    }
}

// transpose in[R][C] f32 -> out[C][R] half (R,C multiples of 32)
__device__ __forceinline__ void do_transpose(const float* in, __half* out, int R, int C,
                                             int bx, int by) {
    __shared__ float tile[32][33];
    int x = bx + threadIdx.x;
    #pragma unroll
    for (int i = 0; i < 4; i++) {
        int y = by + threadIdx.y + i * 8;
        if (y < R && x < C) tile[threadIdx.y + i * 8][threadIdx.x] = in[(size_t)y * C + x];
    }
    __syncthreads();
    int xo = by + threadIdx.x;
    #pragma unroll
    for (int i = 0; i < 4; i++) {
        int yo = bx + threadIdx.y + i * 8;
        if (yo < C && xo < R) out[(size_t)yo * R + xo] = __float2half(tile[threadIdx.x][threadIdx.y + i * 8]);
    }
}

// batched 256x256 transposes: z selects {Wv, Woff, Wout}
__global__ void transpose3_kernel(const float* __restrict__ Wv, const float* __restrict__ Woff,
                                  const float* __restrict__ Wout) {
    const float* in = (blockIdx.z == 0) ? Wv : (blockIdx.z == 1) ? Woff : Wout;
    __half* out = (blockIdx.z == 0) ? g_Wvt : (blockIdx.z == 1) ? g_Wpackt : g_Woutt;
    do_transpose(in, out, 256, 256, blockIdx.x * 32, blockIdx.y * 32);
}

__global__ void transpose_h_kernel(const float* __restrict__ in, __half* __restrict__ out,
                                   int R, int C) {
    do_transpose(in, out, R, C, blockIdx.x * 32, blockIdx.y * 32);
}

// ---------------- fp16 tensor-core GEMM (m16n8k16, fp32 accum) ----------------
// C[M,N] = A[M,K] @ Bt[N,K]^T + bias. BM=128, BN=128, BK=32, 256 threads,
// 8 warps (4M x 2N), warp tile 32x64. 3-stage cp.async ring, one sync per k-tile.

__device__ __forceinline__ void mma_f16(float* d, const uint32_t* a, const uint32_t* b) {
    asm volatile(
        "mma.sync.aligned.m16n8k16.row.col.f32.f16.f16.f32 "
        "{%0,%1,%2,%3}, {%4,%5,%6,%7}, {%8,%9}, {%0,%1,%2,%3};\n"
        : "+f"(d[0]), "+f"(d[1]), "+f"(d[2]), "+f"(d[3])
        : "r"(a[0]), "r"(a[1]), "r"(a[2]), "r"(a[3]), "r"(b[0]), "r"(b[1]));
}

__device__ __forceinline__ void cp_async16(uint32_t saddr, const void* gptr, int srcbytes) {
    asm volatile("cp.async.cg.shared.global [%0], [%1], 16, %2;\n"
                 :: "r"(saddr), "l"(gptr), "r"(srcbytes));
}
__device__ __forceinline__ void cp_commit() { asm volatile("cp.async.commit_group;\n"); }
template<int N>
__device__ __forceinline__ void cp_wait() { asm volatile("cp.async.wait_group %0;\n" :: "n"(N)); }

#define HSTRIDE 40                          // halves per row (80B, 16B aligned, conflict-free)
#define TILE_H (128*HSTRIDE)
#define STAGE_BYTES (2*TILE_H*2)            // 20480 B
#define GEMM_DSMEM (3*STAGE_BYTES)          // 61440 B

template<bool RELU, bool HALF_OUT>
__global__ void __launch_bounds__(256) hgemm_kernel(
    const __half* __restrict__ A, const __half* __restrict__ Bt,
    const float* __restrict__ bias, void* __restrict__ Cv,
    int M, int N, int K)
{
    extern __shared__ __align__(16) char smem_raw[];
    const uint32_t smem_u = (uint32_t)__cvta_generic_to_shared(smem_raw);

    const int tid = threadIdx.x;
    const int wid = tid >> 5;
    const int lane = tid & 31;
    const int bm = blockIdx.y * 128;
    const int bn = blockIdx.x * 128;
    const int wm = (wid & 3) * 32;
    const int wn = (wid >> 2) * 64;
    const int r = lane >> 2;
    const int c = lane & 3;

    const int i_row0 = tid >> 2, i_ch0 = tid & 3;
    const int i_row1 = (tid + 256) >> 2, i_ch1 = tid & 3;

    float acc[2][8][4];
    #pragma unroll
    for (int i = 0; i < 2; i++)
        #pragma unroll
        for (int j = 0; j < 8; j++)
            #pragma unroll
            for (int k = 0; k < 4; k++) acc[i][j][k] = 0.f;

    const int ktiles = K >> 5;

    auto issue_tile = [&](int kt, int s) {
        const int kk = kt * 32;
        const uint32_t sb = smem_u + s * STAGE_BYTES;
        {
            int gr = bm + i_row0;
            cp_async16(sb + (i_row0 * HSTRIDE + i_ch0 * 8) * 2,
                       A + (size_t)gr * K + kk + i_ch0 * 8, (gr < M) ? 16 : 0);
            gr = bm + i_row1;
            cp_async16(sb + (i_row1 * HSTRIDE + i_ch1 * 8) * 2,
                       A + (size_t)gr * K + kk + i_ch1 * 8, (gr < M) ? 16 : 0);
        }
        {
            const uint32_t bb = sb + TILE_H * 2;
            cp_async16(bb + (i_row0 * HSTRIDE + i_ch0 * 8) * 2,
                       Bt + (size_t)(bn + i_row0) * K + kk + i_ch0 * 8, 16);
            cp_async16(bb + (i_row1 * HSTRIDE + i_ch1 * 8) * 2,
                       Bt + (size_t)(bn + i_row1) * K + kk + i_ch1 * 8, 16);
        }
        cp_commit();
    };

    issue_tile(0, 0);
    if (ktiles > 1) issue_tile(1, 1); else cp_commit();

    for (int kt = 0; kt < ktiles; kt++) {
        const int cur = kt % 3;
        cp_wait<1>();
        __syncthreads();

        if (kt + 2 < ktiles) issue_tile(kt + 2, (kt + 2) % 3);
        else cp_commit();

        const __half* As = (const __half*)(smem_raw + cur * STAGE_BYTES);
        const __half* Bs = As + TILE_H;

        #pragma unroll
        for (int ks = 0; ks < 2; ks++) {
            const int k0 = ks * 16 + c * 2;
            uint32_t af[2][4], bf[8][2];
            #pragma unroll
            for (int mt = 0; mt < 2; mt++) {
                const __half* ar = As + (wm + mt * 16 + r) * HSTRIDE + k0;
                af[mt][0] = *(const uint32_t*)(ar);
                af[mt][1] = *(const uint32_t*)(ar + 8 * HSTRIDE);
                af[mt][2] = *(const uint32_t*)(ar + 8);
                af[mt][3] = *(const uint32_t*)(ar + 8 * HSTRIDE + 8);
            }
            #pragma unroll
            for (int nt = 0; nt < 8; nt++) {
                const __half* br = Bs + (wn + nt * 8 + r) * HSTRIDE + k0;
                bf[nt][0] = *(const uint32_t*)(br);
                bf[nt][1] = *(const uint32_t*)(br + 8);
            }
            #pragma unroll
            for (int mt = 0; mt < 2; mt++)
                #pragma unroll
                for (int nt = 0; nt < 8; nt++)
                    mma_f16(acc[mt][nt], af[mt], bf[nt]);
        }
        __syncthreads();
    }

    // ---- epilogue ----
    #pragma unroll
    for (int mt = 0; mt < 2; mt++) {
        #pragma unroll
        for (int nt = 0; nt < 8; nt++) {
            int col = bn + wn + nt * 8 + 2 * c;
            float b0 = __ldg(bias + col), b1 = __ldg(bias + col + 1);
            int row0 = bm + wm + mt * 16 + r;
            int row1 = row0 + 8;
            float v0 = acc[mt][nt][0] + b0, v1 = acc[mt][nt][1] + b1;
            float v2 = acc[mt][nt][2] + b0, v3 = acc[mt][nt][3] + b1;
            if (RELU) {
                v0 = fmaxf(v0, 0.f); v1 = fmaxf(v1, 0.f);
                v2 = fmaxf(v2, 0.f); v3 = fmaxf(v3, 0.f);
            }
            if (HALF_OUT) {
                __half* Ch = (__half*)Cv;
                if (row0 < M) *(__half2*)(Ch + (size_t)row0 * N + col) = __floats2half2_rn(v0, v1);
                if (row1 < M) *(__half2*)(Ch + (size_t)row1 * N + col) = __floats2half2_rn(v2, v3);
            } else {
                float* Cf = (float*)Cv;
                if (row0 < M) *(float2*)(Cf + (size_t)row0 * N + col) = make_float2(v0, v1);
                if (row1 < M) *(float2*)(Cf + (size_t)row1 * N + col) = make_float2(v2, v3);
            }
        }
    }
}

// ---------------- deformable sampling: one warp per (token, head), half value ----------------
__global__ void __launch_bounds__(256) sample_kernel(const float* __restrict__ rp, int T)
{
    const int t = blockIdx.x;
    if (t >= T) return;
    const int h = threadIdx.x >> 5;
    const int lane = threadIdx.x & 31;
    const unsigned FULL = 0xffffffffu;

    const float* raw = g_offattn + (size_t)t * 384;
    float offv = raw[h * 32 + lane];
    float av = (lane < 16) ? raw[256 + h * 16 + lane] : -1e30f;
    float m = av;
    #pragma unroll
    for (int o = 16; o; o >>= 1) m = fmaxf(m, __shfl_xor_sync(FULL, m, o));
    float e = (lane < 16) ? __expf(av - m) : 0.f;
    float s = e;
    #pragma unroll
    for (int o = 16; o; o >>= 1) s += __shfl_xor_sync(FULL, s, o);
    const float anorm = e / s;

    float refv = (lane < 8) ? rp[(size_t)t * 8 + lane] : 0.f;

    const int LSa[4] = {0, 10000, 12500, 13125};
    const int Wla[4] = {100, 50, 25, 13};

    const int p = lane;
    const int l = (p >> 2) & 3;
    const int Wi = Wla[l];
    float rx = __shfl_sync(FULL, refv, 2 * l);
    float ry = __shfl_sync(FULL, refv, 2 * l + 1);
    float ox = __shfl_sync(FULL, offv, (2 * p) & 31);
    float oy = __shfl_sync(FULL, offv, (2 * p + 1) & 31);

    float x = rx * (float)Wi + ox - 0.5f;
    float y = ry * (float)Wi + oy - 0.5f;   // H == W for all levels
    float xf = floorf(x), yf = floorf(y);
    int x0 = (int)xf, y0 = (int)yf;
    float wx1 = x - xf, wy1 = y - yf;
    float wx0 = 1.f - wx1, wy0 = 1.f - wy1;

    int   idxs[4];
    float ws[4];
    #pragma unroll
    for (int tap = 0; tap < 4; tap++) {
        int dx = tap & 1, dy = tap >> 1;
        int xi = x0 + dx, yi = y0 + dy;
        bool valid = (xi >= 0) & (xi < Wi) & (yi >= 0) & (yi < Wi);
        float w = (dx ? wx1 : wx0) * (dy ? wy1 : wy0) * anorm;
        int xic = min(max(xi, 0), Wi - 1);
        int yic = min(max(yi, 0), Wi - 1);
        idxs[tap] = LSa[l] + yic * Wi + xic;
        ws[tap] = valid ? w : 0.f;
    }

    const int n = (t >= LQ) ? 1 : 0;
    const __half* vbase = g_value_h + ((size_t)n * LQ) * 256 + h * 32 + lane;

    float acc0 = 0.f, acc1 = 0.f, acc2 = 0.f, acc3 = 0.f;
    #pragma unroll
    for (int q = 0; q < 16; q++) {
        int i0 = __shfl_sync(FULL, idxs[0], q);
        int i1 = __shfl_sync(FULL, idxs[1], q);
        int i2 = __shfl_sync(FULL, idxs[2], q);
        int i3 = __shfl_sync(FULL, idxs[3], q);
        float w0 = __shfl_sync(FULL, ws[0], q);
        float w1 = __shfl_sync(FULL, ws[1], q);
        float w2 = __shfl_sync(FULL, ws[2], q);
        float w3 = __shfl_sync(FULL, ws[3], q);
        float v0 = __half2float(__ldg(vbase + (size_t)i0 * 256));
        float v1 = __half2float(__ldg(vbase + (size_t)i1 * 256));
        float v2 = __half2float(__ldg(vbase + (size_t)i2 * 256));
        float v3 = __half2float(__ldg(vbase + (size_t)i3 * 256));
        acc0 = fmaf(w0, v0, acc0);
        acc1 = fmaf(w1, v1, acc1);
        acc2 = fmaf(w2, v2, acc2);
        acc3 = fmaf(w3, v3, acc3);
    }
    g_samp_h[(size_t)t * 256 + h * 32 + lane] = __float2half((acc0 + acc1) + (acc2 + acc3));
}

// ---------------- LayerNorm: one warp per token, out = LN(a+b)*g + be ----------------
template<bool WRITEH>
__global__ void __launch_bounds__(256) ln_kernel(
    const float* __restrict__ a, const float* __restrict__ b,
    const float* __restrict__ g, const float* __restrict__ be,
    float* __restrict__ out, __half* __restrict__ outh, int T)
{
    const int warp = (blockIdx.x * blockDim.x + threadIdx.x) >> 5;
    if (warp >= T) return;
    const int lane = threadIdx.x & 31;
    const size_t base = (size_t)warp * 256 + lane * 8;

    float4 a0 = *(const float4*)(a + base);
    float4 a1 = *(const float4*)(a + base + 4);
    float4 b0 = *(const float4*)(b + base);
    float4 b1 = *(const float4*)(b + base + 4);
    float v[8] = {a0.x + b0.x, a0.y + b0.y, a0.z + b0.z, a0.w + b0.w,
                  a1.x + b1.x, a1.y + b1.y, a1.z + b1.z, a1.w + b1.w};
    float s = 0.f, s2 = 0.f;
    #pragma unroll
    for (int i = 0; i < 8; i++) { s += v[i]; s2 = fmaf(v[i], v[i], s2); }
    #pragma unroll
    for (int o = 16; o; o >>= 1) {
        s  += __shfl_xor_sync(0xffffffffu, s,  o);
        s2 += __shfl_xor_sync(0xffffffffu, s2, o);
    }
    float mu = s * (1.f / 256.f);
    float var = s2 * (1.f / 256.f) - mu * mu;
    float rstd = rsqrtf(var + 1e-5f);

    float4 gg0 = *(const float4*)(g + lane * 8);
    float4 gg1 = *(const float4*)(g + lane * 8 + 4);
    float4 bb0 = *(const float4*)(be + lane * 8);
    float4 bb1 = *(const float4*)(be + lane * 8 + 4);
    float gv[8] = {gg0.x, gg0.y, gg0.z, gg0.w, gg1.x, gg1.y, gg1.z, gg1.w};
    float bv[8] = {bb0.x, bb0.y, bb0.z, bb0.w, bb1.x, bb1.y, bb1.z, bb1.w};
    float o0[8];
    #pragma unroll
    for (int i = 0; i < 8; i++) o0[i] = (v[i] - mu) * rstd * gv[i] + bv[i];
    *(float4*)(out + base)     = make_float4(o0[0], o0[1], o0[2], o0[3]);
    *(float4*)(out + base + 4) = make_float4(o0[4], o0[5], o0[6], o0[7]);
    if (WRITEH) {
        __half2* oh = (__half2*)(outh + base);
        oh[0] = __floats2half2_rn(o0[0], o0[1]);
        oh[1] = __floats2half2_rn(o0[2], o0[3]);
        oh[2] = __floats2half2_rn(o0[4], o0[5]);
        oh[3] = __floats2half2_rn(o0[6], o0[7]);
    }
}

// ---------------- host launcher ----------------
extern "C" void kernel_launch(void* const* d_in, const int* in_sizes, int n_in,
                              void* d_out, int out_size)
{
    const float* src   = (const float*)d_in[0];
    const float* pos   = (const float*)d_in[1];
    const float* rp    = (const float*)d_in[2];
    const float* Wv    = (const float*)d_in[5];
    const float* bv    = (const float*)d_in[6];
    const float* Woff  = (const float*)d_in[7];
    const float* boff  = (const float*)d_in[8];
    const float* Wattn = (const float*)d_in[9];
    const float* battn = (const float*)d_in[10];
    const float* Wout  = (const float*)d_in[11];
    const float* bout  = (const float*)d_in[12];
    const float* W1    = (const float*)d_in[13];
    const float* b1    = (const float*)d_in[14];
    const float* W2    = (const float*)d_in[15];
    const float* b2    = (const float*)d_in[16];
    const float* g1    = (const float*)d_in[17];
    const float* be1   = (const float*)d_in[18];
    const float* g2    = (const float*)d_in[19];
    const float* be2   = (const float*)d_in[20];

    const int T = in_sizes[0] / DMODEL;   // N * Lq

    float  *p_offattn, *p_x, *p_x2, *p_f, *p_bpack;
    __half *p_value_h, *p_src_h, *p_q_h, *p_samp_h, *p_x_h, *p_h_h;
    __half *p_Wvt, *p_Wpackt, *p_Woutt, *p_W1t, *p_W2t;
    cudaGetSymbolAddress((void**)&p_offattn, g_offattn);
    cudaGetSymbolAddress((void**)&p_x,       g_x);
    cudaGetSymbolAddress((void**)&p_x2,      g_x2);
    cudaGetSymbolAddress((void**)&p_f,       g_fbuf);
    cudaGetSymbolAddress((void**)&p_bpack,   g_bpack);
    cudaGetSymbolAddress((void**)&p_value_h, g_value_h);
    cudaGetSymbolAddress((void**)&p_src_h,   g_src_h);
    cudaGetSymbolAddress((void**)&p_q_h,     g_q_h);
    cudaGetSymbolAddress((void**)&p_samp_h,  g_samp_h);
    cudaGetSymbolAddress((void**)&p_x_h,     g_x_h);
    cudaGetSymbolAddress((void**)&p_h_h,     g_h_h);
    cudaGetSymbolAddress((void**)&p_Wvt,     g_Wvt);
    cudaGetSymbolAddress((void**)&p_Wpackt,  g_Wpackt);
    cudaGetSymbolAddress((void**)&p_Woutt,   g_Woutt);
    cudaGetSymbolAddress((void**)&p_W1t,     g_W1t);
    cudaGetSymbolAddress((void**)&p_W2t,     g_W2t);

    cudaFuncSetAttribute(hgemm_kernel<false, false>, cudaFuncAttributeMaxDynamicSharedMemorySize, GEMM_DSMEM);
    cudaFuncSetAttribute(hgemm_kernel<false, true>,  cudaFuncAttributeMaxDynamicSharedMemorySize, GEMM_DSMEM);
    cudaFuncSetAttribute(hgemm_kernel<true,  true>,  cudaFuncAttributeMaxDynamicSharedMemorySize, GEMM_DSMEM);

    const int MB = (T + 127) / 128;
    const int n4 = T * DMODEL / 4;
    dim3 tb(32, 8);

    // ---- prep ----
    transpose3_kernel<<<dim3(8, 8, 3), tb>>>(Wv, Woff, Wout);
    transpose_h_kernel<<<dim3(4, 8),  tb>>>(Wattn, p_Wpackt + 65536, 256, 128);
    transpose_h_kernel<<<dim3(32, 8), tb>>>(W1, p_W1t, 256, 1024);
    transpose_h_kernel<<<dim3(8, 32), tb>>>(W2, p_W2t, 1024, 256);
    pack_b_kernel<<<3, 128>>>(boff, battn);
    prep_act_kernel<<<(n4 + 255) / 256, 256>>>(src, pos, n4);

    // 1. value = src @ Wv + bv            (half out, sampling source)
    hgemm_kernel<false, true><<<dim3(2, MB), 256, GEMM_DSMEM>>>(p_src_h, p_Wvt, bv, p_value_h, T, 256, 256);

    // 2. offattn = q @ [W_off|W_attn] + b (f32 out)
    hgemm_kernel<false, false><<<dim3(3, MB), 256, GEMM_DSMEM>>>(p_q_h, p_Wpackt, p_bpack, p_offattn, T, 384, 256);

    // 3. deformable sampling + softmax fused (half out)
    sample_kernel<<<T, 256>>>(rp, T);

    // 4. x2 = samp @ W_out + b_out        (f32 out)
    hgemm_kernel<false, false><<<dim3(2, MB), 256, GEMM_DSMEM>>>(p_samp_h, p_Woutt, bout, p_x2, T, 256, 256);

    // 5. x = LN(src + x2)                 (f32 + half)
    ln_kernel<true><<<(T * 32 + 255) / 256, 256>>>(src, p_x2, g1, be1, p_x, p_x_h, T);

    // 6. h = relu(x @ W1 + b1)            (half out only)
    hgemm_kernel<true, true><<<dim3(8, MB), 256, GEMM_DSMEM>>>(p_x_h, p_W1t, b1, p_h_h, T, 1024, 256);

    // 7. f = h @ W2 + b2                  (f32 out)
    hgemm_kernel<false, false><<<dim3(2, MB), 256, GEMM_DSMEM>>>(p_h_h, p_W2t, b2, p_f, T, 256, 1024);

    // 8. out = LN(x + f)
    ln_kernel<false><<<(T * 32 + 255) / 256, 256>>>(p_x, p_f, g2, be2, (float*)d_out, nullptr, T);
}

// round 8
// speedup vs baseline: 4.6191x; 1.2432x over previous
#include <cuda_runtime.h>
#include <cuda_fp16.h>
#include <math.h>
#include <stdint.h>

#define LQ 13294
#define DMODEL 256
#define MAXN 2

// ---------------- scratch (device globals; no allocation) ----------------
__device__ float  g_offattn[MAXN*LQ*384];      // [T,384] f32
__device__ float  g_x[MAXN*LQ*DMODEL];         // [T,256] f32 (residual)
__device__ float  g_x2[MAXN*LQ*DMODEL];        // [T,256] f32
__device__ float  g_fbuf[MAXN*LQ*DMODEL];      // [T,256] f32
__device__ __half g_value_h[MAXN*LQ*DMODEL];   // [T,256] half (sampling source)
__device__ __half g_src_h[MAXN*LQ*DMODEL];     // half GEMM inputs
__device__ __half g_q_h[MAXN*LQ*DMODEL];
__device__ __half g_samp_h[MAXN*LQ*DMODEL];
__device__ __half g_x_h[MAXN*LQ*DMODEL];
__device__ __half g_h_h[MAXN*LQ*1024];         // FFN intermediate, half only
// transposed half weights [N][K]
__device__ __half g_Wvt[256*256];
__device__ __half g_Wpackt[384*256];
__device__ __half g_Woutt[256*256];
__device__ __half g_W1t[1024*256];
__device__ __half g_W2t[256*1024];
__device__ float  g_bpack[384];

// ---------------- prep: all weight transposes + bias pack in ONE kernel ----------------
__device__ __forceinline__ void do_transpose(const float* in, __half* out, int R, int C,
                                             int bx, int by) {
    __shared__ float tile[32][33];
    int x = bx + threadIdx.x;
    #pragma unroll
    for (int i = 0; i < 4; i++) {
        int y = by + threadIdx.y + i * 8;
        if (y < R && x < C) tile[threadIdx.y + i * 8][threadIdx.x] = in[(size_t)y * C + x];
    }
    __syncthreads();
    int xo = by + threadIdx.x;
    #pragma unroll
    for (int i = 0; i < 4; i++) {
        int yo = bx + threadIdx.y + i * 8;
        if (yo < C && xo < R) out[(size_t)yo * R + xo] = __float2half(tile[threadIdx.x][threadIdx.y + i * 8]);
    }
}

// tiles: [0,64) Wv | [64,128) Woff | [128,192) Wout | [192,224) Wattn |
//        [224,480) W1 | [480,736) W2 | 736..737 bias pack
__global__ void prep_w_kernel(const float* __restrict__ Wv, const float* __restrict__ Woff,
                              const float* __restrict__ Wout, const float* __restrict__ Wattn,
                              const float* __restrict__ W1, const float* __restrict__ W2,
                              const float* __restrict__ boff, const float* __restrict__ battn) {
    int id = blockIdx.x;
    if (id < 64)       do_transpose(Wv,   g_Wvt,            256, 256,  (id & 7) * 32,          (id >> 3) * 32);
    else if (id < 128) do_transpose(Woff, g_Wpackt,         256, 256,  ((id - 64) & 7) * 32,   ((id - 64) >> 3) * 32);
    else if (id < 192) do_transpose(Wout, g_Woutt,          256, 256,  ((id - 128) & 7) * 32,  ((id - 128) >> 3) * 32);
    else if (id < 224) do_transpose(Wattn, g_Wpackt + 65536, 256, 128, ((id - 192) & 3) * 32,  ((id - 192) >> 2) * 32);
    else if (id < 480) do_transpose(W1,   g_W1t,            256, 1024, ((id - 224) & 31) * 32, ((id - 224) >> 5) * 32);
    else if (id < 736) do_transpose(W2,   g_W2t,            1024, 256, ((id - 480) & 7) * 32,  ((id - 480) >> 3) * 32);
    else {
        int tid = threadIdx.y * 32 + threadIdx.x;
        if (id == 736) g_bpack[tid] = boff[tid];
        else if (tid < 128) g_bpack[256 + tid] = battn[tid];
    }
}

// src_h = half(src); q_h = half(src + pos)
__global__ void prep_act_kernel(const float* __restrict__ src, const float* __restrict__ pos,
                                int n4) {
    int i = blockIdx.x * blockDim.x + threadIdx.x;
    if (i < n4) {
        float4 vs = ((const float4*)src)[i];
        float4 vp = ((const float4*)pos)[i];
        __half2* os = (__half2*)g_src_h;
        __half2* oq = (__half2*)g_q_h;
        os[2 * i]     = __floats2half2_rn(vs.x, vs.y);
        os[2 * i + 1] = __floats2half2_rn(vs.z, vs.w);
        oq[2 * i]     = __floats2half2_rn(vs.x + vp.x, vs.y + vp.y);
        oq[2 * i + 1] = __floats2half2_rn(vs.z + vp.z, vs.w + vp.w);
    }
}

// ---------------- fp16 tensor-core GEMM (m16n8k16, fp32 accum) ----------------
__device__ __forceinline__ void mma_f16(float* d, const uint32_t* a, const uint32_t* b) {
    asm volatile(
        "mma.sync.aligned.m16n8k16.row.col.f32.f16.f16.f32 "
        "{%0,%1,%2,%3}, {%4,%5,%6,%7}, {%8,%9}, {%0,%1,%2,%3};\n"
        : "+f"(d[0]), "+f"(d[1]), "+f"(d[2]), "+f"(d[3])
        : "r"(a[0]), "r"(a[1]), "r"(a[2]), "r"(a[3]), "r"(b[0]), "r"(b[1]));
}

__device__ __forceinline__ void cp_async16(uint32_t saddr, const void* gptr, int srcbytes) {
    asm volatile("cp.async.cg.shared.global [%0], [%1], 16, %2;\n"
                 :: "r"(saddr), "l"(gptr), "r"(srcbytes));
}
__device__ __forceinline__ void cp_commit() { asm volatile("cp.async.commit_group;\n"); }
template<int N>
__device__ __forceinline__ void cp_wait() { asm volatile("cp.async.wait_group %0;\n" :: "n"(N)); }

#define HSTRIDE 40
#define TILE_H (128*HSTRIDE)
#define STAGE_BYTES (2*TILE_H*2)
#define GEMM_DSMEM (3*STAGE_BYTES)

template<bool RELU, bool HALF_OUT>
__global__ void __launch_bounds__(256) hgemm_kernel(
    const __half* __restrict__ A, const __half* __restrict__ Bt,
    const float* __restrict__ bias, void* __restrict__ Cv,
    int M, int N, int K)
{
    extern __shared__ __align__(16) char smem_raw[];
    const uint32_t smem_u = (uint32_t)__cvta_generic_to_shared(smem_raw);

    const int tid = threadIdx.x;
    const int wid = tid >> 5;
    const int lane = tid & 31;
    const int bm = blockIdx.y * 128;
    const int bn = blockIdx.x * 128;
    const int wm = (wid & 3) * 32;
    const int wn = (wid >> 2) * 64;
    const int r = lane >> 2;
    const int c = lane & 3;

    const int i_row0 = tid >> 2, i_ch0 = tid & 3;
    const int i_row1 = (tid + 256) >> 2, i_ch1 = tid & 3;

    float acc[2][8][4];
    #pragma unroll
    for (int i = 0; i < 2; i++)
        #pragma unroll
        for (int j = 0; j < 8; j++)
            #pragma unroll
            for (int k = 0; k < 4; k++) acc[i][j][k] = 0.f;

    const int ktiles = K >> 5;

    auto issue_tile = [&](int kt, int s) {
        const int kk = kt * 32;
        const uint32_t sb = smem_u + s * STAGE_BYTES;
        {
            int gr = bm + i_row0;
            cp_async16(sb + (i_row0 * HSTRIDE + i_ch0 * 8) * 2,
                       A + (size_t)gr * K + kk + i_ch0 * 8, (gr < M) ? 16 : 0);
            gr = bm + i_row1;
            cp_async16(sb + (i_row1 * HSTRIDE + i_ch1 * 8) * 2,
                       A + (size_t)gr * K + kk + i_ch1 * 8, (gr < M) ? 16 : 0);
        }
        {
            const uint32_t bb = sb + TILE_H * 2;
            cp_async16(bb + (i_row0 * HSTRIDE + i_ch0 * 8) * 2,
                       Bt + (size_t)(bn + i_row0) * K + kk + i_ch0 * 8, 16);
            cp_async16(bb + (i_row1 * HSTRIDE + i_ch1 * 8) * 2,
                       Bt + (size_t)(bn + i_row1) * K + kk + i_ch1 * 8, 16);
        }
        cp_commit();
    };

    issue_tile(0, 0);
    if (ktiles > 1) issue_tile(1, 1); else cp_commit();

    for (int kt = 0; kt < ktiles; kt++) {
        const int cur = kt % 3;
        cp_wait<1>();
        __syncthreads();

        if (kt + 2 < ktiles) issue_tile(kt + 2, (kt + 2) % 3);
        else cp_commit();

        const __half* As = (const __half*)(smem_raw + cur * STAGE_BYTES);
        const __half* Bs = As + TILE_H;

        #pragma unroll
        for (int ks = 0; ks < 2; ks++) {
            const int k0 = ks * 16 + c * 2;
            uint32_t af[2][4], bf[8][2];
            #pragma unroll
            for (int mt = 0; mt < 2; mt++) {
                const __half* ar = As + (wm + mt * 16 + r) * HSTRIDE + k0;
                af[mt][0] = *(const uint32_t*)(ar);
                af[mt][1] = *(const uint32_t*)(ar + 8 * HSTRIDE);
                af[mt][2] = *(const uint32_t*)(ar + 8);
                af[mt][3] = *(const uint32_t*)(ar + 8 * HSTRIDE + 8);
            }
            #pragma unroll
            for (int nt = 0; nt < 8; nt++) {
                const __half* br = Bs + (wn + nt * 8 + r) * HSTRIDE + k0;
                bf[nt][0] = *(const uint32_t*)(br);
                bf[nt][1] = *(const uint32_t*)(br + 8);
            }
            #pragma unroll
            for (int mt = 0; mt < 2; mt++)
                #pragma unroll
                for (int nt = 0; nt < 8; nt++)
                    mma_f16(acc[mt][nt], af[mt], bf[nt]);
        }
        __syncthreads();
    }

    #pragma unroll
    for (int mt = 0; mt < 2; mt++) {
        #pragma unroll
        for (int nt = 0; nt < 8; nt++) {
            int col = bn + wn + nt * 8 + 2 * c;
            float b0 = __ldg(bias + col), b1 = __ldg(bias + col + 1);
            int row0 = bm + wm + mt * 16 + r;
            int row1 = row0 + 8;
            float v0 = acc[mt][nt][0] + b0, v1 = acc[mt][nt][1] + b1;
            float v2 = acc[mt][nt][2] + b0, v3 = acc[mt][nt][3] + b1;
            if (RELU) {
                v0 = fmaxf(v0, 0.f); v1 = fmaxf(v1, 0.f);
                v2 = fmaxf(v2, 0.f); v3 = fmaxf(v3, 0.f);
            }
            if (HALF_OUT) {
                __half* Ch = (__half*)Cv;
                if (row0 < M) *(__half2*)(Ch + (size_t)row0 * N + col) = __floats2half2_rn(v0, v1);
                if (row1 < M) *(__half2*)(Ch + (size_t)row1 * N + col) = __floats2half2_rn(v2, v3);
            } else {
                float* Cf = (float*)Cv;
                if (row0 < M) *(float2*)(Cf + (size_t)row0 * N + col) = make_float2(v0, v1);
                if (row1 < M) *(float2*)(Cf + (size_t)row1 * N + col) = make_float2(v2, v3);
            }
        }
    }
}

// ---------------- deformable sampling: 2 heads per warp, half2 gathers ----------------
// 128 threads/token (4 warps). Lane = (head_sel = lane>>4, point = lane&15).
__global__ void __launch_bounds__(128) sample_kernel(const float* __restrict__ rp, int T)
{
    const int t = blockIdx.x;
    if (t >= T) return;
    const int warp = threadIdx.x >> 5;
    const int lane = threadIdx.x & 31;
    const unsigned FULL = 0xffffffffu;

    const int hsel = lane >> 4;          // 0 or 1
    const int p = lane & 15;             // point id
    const int h = warp * 2 + hsel;       // head id

    const float* raw = g_offattn + (size_t)t * 384;

    // offsets: this lane's (h, p) pair
    float2 off = *(const float2*)(raw + h * 32 + p * 2);
    // attn logit + softmax within 16-lane group
    float av = raw[256 + h * 16 + p];
    float m = av;
    #pragma unroll
    for (int o = 8; o; o >>= 1) m = fmaxf(m, __shfl_xor_sync(FULL, m, o));
    float e = __expf(av - m);
    float s = e;
    #pragma unroll
    for (int o = 8; o; o >>= 1) s += __shfl_xor_sync(FULL, s, o);
    const float anorm = e / s;

    const int LSa[4] = {0, 10000, 12500, 13125};
    const int Wla[4] = {100, 50, 25, 13};
    const int l = p >> 2;
    const int Wi = Wla[l];
    const float rx = __ldg(rp + (size_t)t * 8 + 2 * l);
    const float ry = __ldg(rp + (size_t)t * 8 + 2 * l + 1);

    float x = rx * (float)Wi + off.x - 0.5f;
    float y = ry * (float)Wi + off.y - 0.5f;   // H == W for all levels
    float xf = floorf(x), yf = floorf(y);
    int x0 = (int)xf, y0 = (int)yf;
    float wx1 = x - xf, wy1 = y - yf;
    float wx0 = 1.f - wx1, wy0 = 1.f - wy1;

    int   idxs[4];
    float ws[4];
    #pragma unroll
    for (int tap = 0; tap < 4; tap++) {
        int dx = tap & 1, dy = tap >> 1;
        int xi = x0 + dx, yi = y0 + dy;
        bool valid = (xi >= 0) & (xi < Wi) & (yi >= 0) & (yi < Wi);
        float w = (dx ? wx1 : wx0) * (dy ? wy1 : wy0) * anorm;
        int xic = min(max(xi, 0), Wi - 1);
        int yic = min(max(yi, 0), Wi - 1);
        idxs[tap] = LSa[l] + yic * Wi + xic;
        ws[tap] = valid ? w : 0.f;
    }

    // gather: lane covers 2 channels of its head
    const int n = (t >= LQ) ? 1 : 0;
    const int ch = p * 2;                                 // channel pair base within head
    const size_t hbase = ((size_t)n * LQ) * 256 + h * 32 + ch;   // even
    const __half2* vb = (const __half2*)g_value_h + (hbase >> 1);

    float2 a0 = {0.f, 0.f}, a1 = {0.f, 0.f}, a2 = {0.f, 0.f}, a3 = {0.f, 0.f};
    const int lbase = lane & 16;                          // source group base
    #pragma unroll
    for (int pi = 0; pi < 16; pi++) {
        const int sl = lbase + pi;
        int i0 = __shfl_sync(FULL, idxs[0], sl);
        int i1 = __shfl_sync(FULL, idxs[1], sl);
        int i2 = __shfl_sync(FULL, idxs[2], sl);
        int i3 = __shfl_sync(FULL, idxs[3], sl);
        float w0 = __shfl_sync(FULL, ws[0], sl);
        float w1 = __shfl_sync(FULL, ws[1], sl);
        float w2 = __shfl_sync(FULL, ws[2], sl);
        float w3 = __shfl_sync(FULL, ws[3], sl);
        float2 v0 = __half22float2(__ldg(vb + (size_t)i0 * 128));
        float2 v1 = __half22float2(__ldg(vb + (size_t)i1 * 128));
        float2 v2 = __half22float2(__ldg(vb + (size_t)i2 * 128));
        float2 v3 = __half22float2(__ldg(vb + (size_t)i3 * 128));
        a0.x = fmaf(w0, v0.x, a0.x); a0.y = fmaf(w0, v0.y, a0.y);
        a1.x = fmaf(w1, v1.x, a1.x); a1.y = fmaf(w1, v1.y, a1.y);
        a2.x = fmaf(w2, v2.x, a2.x); a2.y = fmaf(w2, v2.y, a2.y);
        a3.x = fmaf(w3, v3.x, a3.x); a3.y = fmaf(w3, v3.y, a3.y);
    }
    float ox = (a0.x + a1.x) + (a2.x + a3.x);
    float oy = (a0.y + a1.y) + (a2.y + a3.y);
    __half2* outp = (__half2*)g_samp_h + (((size_t)t * 256 + h * 32 + ch) >> 1);
    *outp = __floats2half2_rn(ox, oy);
}

// ---------------- LayerNorm: one warp per token, out = LN(a+b)*g + be ----------------
template<bool WRITEH>
__global__ void __launch_bounds__(256) ln_kernel(
    const float* __restrict__ a, const float* __restrict__ b,
    const float* __restrict__ g, const float* __restrict__ be,
    float* __restrict__ out, __half* __restrict__ outh, int T)
{
    const int warp = (blockIdx.x * blockDim.x + threadIdx.x) >> 5;
    if (warp >= T) return;
    const int lane = threadIdx.x & 31;
    const size_t base = (size_t)warp * 256 + lane * 8;

    float4 a0 = *(const float4*)(a + base);
    float4 a1 = *(const float4*)(a + base + 4);
    float4 b0 = *(const float4*)(b + base);
    float4 b1 = *(const float4*)(b + base + 4);
    float v[8] = {a0.x + b0.x, a0.y + b0.y, a0.z + b0.z, a0.w + b0.w,
                  a1.x + b1.x, a1.y + b1.y, a1.z + b1.z, a1.w + b1.w};
    float s = 0.f, s2 = 0.f;
    #pragma unroll
    for (int i = 0; i < 8; i++) { s += v[i]; s2 = fmaf(v[i], v[i], s2); }
    #pragma unroll
    for (int o = 16; o; o >>= 1) {
        s  += __shfl_xor_sync(0xffffffffu, s,  o);
        s2 += __shfl_xor_sync(0xffffffffu, s2, o);
    }
    float mu = s * (1.f / 256.f);
    float var = s2 * (1.f / 256.f) - mu * mu;
    float rstd = rsqrtf(var + 1e-5f);

    float4 gg0 = *(const float4*)(g + lane * 8);
    float4 gg1 = *(const float4*)(g + lane * 8 + 4);
    float4 bb0 = *(const float4*)(be + lane * 8);
    float4 bb1 = *(const float4*)(be + lane * 8 + 4);
    float gv[8] = {gg0.x, gg0.y, gg0.z, gg0.w, gg1.x, gg1.y, gg1.z, gg1.w};
    float bv[8] = {bb0.x, bb0.y, bb0.z, bb0.w, bb1.x, bb1.y, bb1.z, bb1.w};
    float o0[8];
    #pragma unroll
    for (int i = 0; i < 8; i++) o0[i] = (v[i] - mu) * rstd * gv[i] + bv[i];
    *(float4*)(out + base)     = make_float4(o0[0], o0[1], o0[2], o0[3]);
    *(float4*)(out + base + 4) = make_float4(o0[4], o0[5], o0[6], o0[7]);
    if (WRITEH) {
        __half2* oh = (__half2*)(outh + base);
        oh[0] = __floats2half2_rn(o0[0], o0[1]);
        oh[1] = __floats2half2_rn(o0[2], o0[3]);
        oh[2] = __floats2half2_rn(o0[4], o0[5]);
        oh[3] = __floats2half2_rn(o0[6], o0[7]);
    }
}

// ---------------- host launcher ----------------
extern "C" void kernel_launch(void* const* d_in, const int* in_sizes, int n_in,
                              void* d_out, int out_size)
{
    const float* src   = (const float*)d_in[0];
    const float* pos   = (const float*)d_in[1];
    const float* rp    = (const float*)d_in[2];
    const float* Wv    = (const float*)d_in[5];
    const float* bv    = (const float*)d_in[6];
    const float* Woff  = (const float*)d_in[7];
    const float* boff  = (const float*)d_in[8];
    const float* Wattn = (const float*)d_in[9];
    const float* battn = (const float*)d_in[10];
    const float* Wout  = (const float*)d_in[11];
    const float* bout  = (const float*)d_in[12];
    const float* W1    = (const float*)d_in[13];
    const float* b1    = (const float*)d_in[14];
    const float* W2    = (const float*)d_in[15];
    const float* b2    = (const float*)d_in[16];
    const float* g1    = (const float*)d_in[17];
    const float* be1   = (const float*)d_in[18];
    const float* g2    = (const float*)d_in[19];
    const float* be2   = (const float*)d_in[20];

    const int T = in_sizes[0] / DMODEL;   // N * Lq

    float  *p_offattn, *p_x, *p_x2, *p_f, *p_bpack;
    __half *p_value_h, *p_src_h, *p_q_h, *p_samp_h, *p_x_h, *p_h_h;
    __half *p_Wvt, *p_Wpackt, *p_Woutt, *p_W1t, *p_W2t;
    cudaGetSymbolAddress((void**)&p_offattn, g_offattn);
    cudaGetSymbolAddress((void**)&p_x,       g_x);
    cudaGetSymbolAddress((void**)&p_x2,      g_x2);
    cudaGetSymbolAddress((void**)&p_f,       g_fbuf);
    cudaGetSymbolAddress((void**)&p_bpack,   g_bpack);
    cudaGetSymbolAddress((void**)&p_value_h, g_value_h);
    cudaGetSymbolAddress((void**)&p_src_h,   g_src_h);
    cudaGetSymbolAddress((void**)&p_q_h,     g_q_h);
    cudaGetSymbolAddress((void**)&p_samp_h,  g_samp_h);
    cudaGetSymbolAddress((void**)&p_x_h,     g_x_h);
    cudaGetSymbolAddress((void**)&p_h_h,     g_h_h);
    cudaGetSymbolAddress((void**)&p_Wvt,     g_Wvt);
    cudaGetSymbolAddress((void**)&p_Wpackt,  g_Wpackt);
    cudaGetSymbolAddress((void**)&p_Woutt,   g_Woutt);
    cudaGetSymbolAddress((void**)&p_W1t,     g_W1t);
    cudaGetSymbolAddress((void**)&p_W2t,     g_W2t);

    cudaFuncSetAttribute(hgemm_kernel<false, false>, cudaFuncAttributeMaxDynamicSharedMemorySize, GEMM_DSMEM);
    cudaFuncSetAttribute(hgemm_kernel<false, true>,  cudaFuncAttributeMaxDynamicSharedMemorySize, GEMM_DSMEM);
    cudaFuncSetAttribute(hgemm_kernel<true,  true>,  cudaFuncAttributeMaxDynamicSharedMemorySize, GEMM_DSMEM);

    const int MB = (T + 127) / 128;
    const int n4 = T * DMODEL / 4;
    dim3 tb(32, 8);

    // ---- prep (2 launches) ----
    prep_w_kernel<<<738, tb>>>(Wv, Woff, Wout, Wattn, W1, W2, boff, battn);
    prep_act_kernel<<<(n4 + 255) / 256, 256>>>(src, pos, n4);

    // 1. value = src @ Wv + bv            (half out, sampling source)
    hgemm_kernel<false, true><<<dim3(2, MB), 256, GEMM_DSMEM>>>(p_src_h, p_Wvt, bv, p_value_h, T, 256, 256);

    // 2. offattn = q @ [W_off|W_attn] + b (f32 out)
    hgemm_kernel<false, false><<<dim3(3, MB), 256, GEMM_DSMEM>>>(p_q_h, p_Wpackt, p_bpack, p_offattn, T, 384, 256);

    // 3. deformable sampling + softmax fused (half out)
    sample_kernel<<<T, 128>>>(rp, T);

    // 4. x2 = samp @ W_out + b_out        (f32 out)
    hgemm_kernel<false, false><<<dim3(2, MB), 256, GEMM_DSMEM>>>(p_samp_h, p_Woutt, bout, p_x2, T, 256, 256);

    // 5. x = LN(src + x2)                 (f32 + half)
    ln_kernel<true><<<(T * 32 + 255) / 256, 256>>>(src, p_x2, g1, be1, p_x, p_x_h, T);

    // 6. h = relu(x @ W1 + b1)            (half out only)
    hgemm_kernel<true, true><<<dim3(8, MB), 256, GEMM_DSMEM>>>(p_x_h, p_W1t, b1, p_h_h, T, 1024, 256);

    // 7. f = h @ W2 + b2                  (f32 out)
    hgemm_kernel<false, false><<<dim3(2, MB), 256, GEMM_DSMEM>>>(p_h_h, p_W2t, b2, p_f, T, 256, 1024);

    // 8. out = LN(x + f)
    ln_kernel<false><<<(T * 32 + 255) / 256, 256>>>(p_x, p_f, g2, be2, (float*)d_out, nullptr, T);
}

// round 9
// speedup vs baseline: 4.7428x; 1.0268x over previous
#include <cuda_runtime.h>
#include <cuda_fp16.h>
#include <math.h>
#include <stdint.h>

#define LQ 13294
#define DMODEL 256
#define MAXN 2

// ---------------- scratch (device globals; no allocation) ----------------
__device__ float  g_offattn[MAXN*LQ*384];      // [T,384] f32
__device__ float  g_x[MAXN*LQ*DMODEL];         // [T,256] f32 (residual)
__device__ float  g_x2[MAXN*LQ*DMODEL];        // [T,256] f32
__device__ float  g_fbuf[MAXN*LQ*DMODEL];      // [T,256] f32
__device__ __half g_value_h[MAXN*LQ*DMODEL];   // [T,256] half (sampling source)
__device__ __half g_src_h[MAXN*LQ*DMODEL];     // half GEMM inputs
__device__ __half g_q_h[MAXN*LQ*DMODEL];
__device__ __half g_samp_h[MAXN*LQ*DMODEL];
__device__ __half g_x_h[MAXN*LQ*DMODEL];
__device__ __half g_h_h[MAXN*LQ*1024];         // FFN intermediate, half only
// transposed half weights [N][K]
__device__ __half g_Wvt[256*256];
__device__ __half g_Wpackt[384*256];
__device__ __half g_Woutt[256*256];
__device__ __half g_W1t[1024*256];
__device__ __half g_W2t[256*1024];
__device__ float  g_bpack[384];

// ---------------- prep: all weight transposes + bias pack in ONE kernel ----------------
__device__ __forceinline__ void do_transpose(const float* in, __half* out, int R, int C,
                                             int bx, int by) {
    __shared__ float tile[32][33];
    int x = bx + threadIdx.x;
    #pragma unroll
    for (int i = 0; i < 4; i++) {
        int y = by + threadIdx.y + i * 8;
        if (y < R && x < C) tile[threadIdx.y + i * 8][threadIdx.x] = in[(size_t)y * C + x];
    }
    __syncthreads();
    int xo = by + threadIdx.x;
    #pragma unroll
    for (int i = 0; i < 4; i++) {
        int yo = bx + threadIdx.y + i * 8;
        if (yo < C && xo < R) out[(size_t)yo * R + xo] = __float2half(tile[threadIdx.x][threadIdx.y + i * 8]);
    }
}

__global__ void prep_w_kernel(const float* __restrict__ Wv, const float* __restrict__ Woff,
                              const float* __restrict__ Wout, const float* __restrict__ Wattn,
                              const float* __restrict__ W1, const float* __restrict__ W2,
                              const float* __restrict__ boff, const float* __restrict__ battn) {
    int id = blockIdx.x;
    if (id < 64)       do_transpose(Wv,   g_Wvt,            256, 256,  (id & 7) * 32,          (id >> 3) * 32);
    else if (id < 128) do_transpose(Woff, g_Wpackt,         256, 256,  ((id - 64) & 7) * 32,   ((id - 64) >> 3) * 32);
    else if (id < 192) do_transpose(Wout, g_Woutt,          256, 256,  ((id - 128) & 7) * 32,  ((id - 128) >> 3) * 32);
    else if (id < 224) do_transpose(Wattn, g_Wpackt + 65536, 256, 128, ((id - 192) & 3) * 32,  ((id - 192) >> 2) * 32);
    else if (id < 480) do_transpose(W1,   g_W1t,            256, 1024, ((id - 224) & 31) * 32, ((id - 224) >> 5) * 32);
    else if (id < 736) do_transpose(W2,   g_W2t,            1024, 256, ((id - 480) & 7) * 32,  ((id - 480) >> 3) * 32);
    else {
        int tid = threadIdx.y * 32 + threadIdx.x;
        if (id == 736) g_bpack[tid] = boff[tid];
        else if (tid < 128) g_bpack[256 + tid] = battn[tid];
    }
}

__global__ void prep_act_kernel(const float* __restrict__ src, const float* __restrict__ pos,
                                int n4) {
    int i = blockIdx.x * blockDim.x + threadIdx.x;
    if (i < n4) {
        float4 vs = ((const float4*)src)[i];
        float4 vp = ((const float4*)pos)[i];
        __half2* os = (__half2*)g_src_h;
        __half2* oq = (__half2*)g_q_h;
        os[2 * i]     = __floats2half2_rn(vs.x, vs.y);
        os[2 * i + 1] = __floats2half2_rn(vs.z, vs.w);
        oq[2 * i]     = __floats2half2_rn(vs.x + vp.x, vs.y + vp.y);
        oq[2 * i + 1] = __floats2half2_rn(vs.z + vp.z, vs.w + vp.w);
    }
}

// ---------------- fp16 tensor-core GEMM (m16n8k16, fp32 accum, ldmatrix) ----------------
__device__ __forceinline__ void mma_f16(float* d, const uint32_t* a, const uint32_t* b) {
    asm volatile(
        "mma.sync.aligned.m16n8k16.row.col.f32.f16.f16.f32 "
        "{%0,%1,%2,%3}, {%4,%5,%6,%7}, {%8,%9}, {%0,%1,%2,%3};\n"
        : "+f"(d[0]), "+f"(d[1]), "+f"(d[2]), "+f"(d[3])
        : "r"(a[0]), "r"(a[1]), "r"(a[2]), "r"(a[3]), "r"(b[0]), "r"(b[1]));
}

__device__ __forceinline__ void ldsm_x4(uint32_t& r0, uint32_t& r1, uint32_t& r2, uint32_t& r3,
                                        uint32_t addr) {
    asm volatile("ldmatrix.sync.aligned.m8n8.x4.shared.b16 {%0,%1,%2,%3}, [%4];"
                 : "=r"(r0), "=r"(r1), "=r"(r2), "=r"(r3) : "r"(addr));
}

__device__ __forceinline__ void cp_async16(uint32_t saddr, const void* gptr, int srcbytes) {
    asm volatile("cp.async.cg.shared.global [%0], [%1], 16, %2;\n"
                 :: "r"(saddr), "l"(gptr), "r"(srcbytes));
}
__device__ __forceinline__ void cp_commit() { asm volatile("cp.async.commit_group;\n"); }
template<int N>
__device__ __forceinline__ void cp_wait() { asm volatile("cp.async.wait_group %0;\n" :: "n"(N)); }

#define HSTRIDE 40
#define TILE_H (128*HSTRIDE)
#define STAGE_BYTES (2*TILE_H*2)            // 20480 B
#define NSTAGE 4
#define GEMM_DSMEM (NSTAGE*STAGE_BYTES)     // 81920 B

template<bool RELU, bool HALF_OUT>
__global__ void __launch_bounds__(256) hgemm_kernel(
    const __half* __restrict__ A, const __half* __restrict__ Bt,
    const float* __restrict__ bias, void* __restrict__ Cv,
    int M, int N, int K)
{
    extern __shared__ __align__(16) char smem_raw[];
    const uint32_t smem_u = (uint32_t)__cvta_generic_to_shared(smem_raw);

    const int tid = threadIdx.x;
    const int wid = tid >> 5;
    const int lane = tid & 31;
    const int bm = blockIdx.y * 128;
    const int bn = blockIdx.x * 128;
    const int wm = (wid & 3) * 32;
    const int wn = (wid >> 2) * 64;
    const int r = lane >> 2;
    const int c = lane & 3;

    const int i_row0 = tid >> 2, i_ch0 = tid & 3;
    const int i_row1 = (tid + 256) >> 2, i_ch1 = tid & 3;

    // ldmatrix per-lane base addresses (stage 0, ks 0)
    const int mrow = lane & 7;
    const int mid = lane >> 3;     // matrix id within x4
    const uint32_t a_base0 = smem_u + (uint32_t)(((wm + (mid & 1) * 8 + mrow) * HSTRIDE + (mid >> 1) * 8) * 2);
    const uint32_t a_base1 = a_base0 + 16 * HSTRIDE * 2;
    uint32_t b_base[4];
    #pragma unroll
    for (int q = 0; q < 4; q++)
        b_base[q] = smem_u + TILE_H * 2 +
                    (uint32_t)(((wn + q * 16 + (mid >> 1) * 8 + mrow) * HSTRIDE + (mid & 1) * 8) * 2);

    float acc[2][8][4];
    #pragma unroll
    for (int i = 0; i < 2; i++)
        #pragma unroll
        for (int j = 0; j < 8; j++)
            #pragma unroll
            for (int k = 0; k < 4; k++) acc[i][j][k] = 0.f;

    const int ktiles = K >> 5;

    auto issue_tile = [&](int kt, int s) {
        const int kk = kt * 32;
        const uint32_t sb = smem_u + s * STAGE_BYTES;
        {
            int gr = bm + i_row0;
            cp_async16(sb + (i_row0 * HSTRIDE + i_ch0 * 8) * 2,
                       A + (size_t)gr * K + kk + i_ch0 * 8, (gr < M) ? 16 : 0);
            gr = bm + i_row1;
            cp_async16(sb + (i_row1 * HSTRIDE + i_ch1 * 8) * 2,
                       A + (size_t)gr * K + kk + i_ch1 * 8, (gr < M) ? 16 : 0);
        }
        {
            const uint32_t bb = sb + TILE_H * 2;
            cp_async16(bb + (i_row0 * HSTRIDE + i_ch0 * 8) * 2,
                       Bt + (size_t)(bn + i_row0) * K + kk + i_ch0 * 8, 16);
            cp_async16(bb + (i_row1 * HSTRIDE + i_ch1 * 8) * 2,
                       Bt + (size_t)(bn + i_row1) * K + kk + i_ch1 * 8, 16);
        }
        cp_commit();
    };

    issue_tile(0, 0);
    if (ktiles > 1) issue_tile(1, 1); else cp_commit();
    if (ktiles > 2) issue_tile(2, 2); else cp_commit();

    for (int kt = 0; kt < ktiles; kt++) {
        const int cur = kt & (NSTAGE - 1);
        cp_wait<2>();
        __syncthreads();

        if (kt + 3 < ktiles) issue_tile(kt + 3, (kt + 3) & (NSTAGE - 1));
        else cp_commit();

        const uint32_t sbase = (uint32_t)(cur * STAGE_BYTES);

        #pragma unroll
        for (int ks = 0; ks < 2; ks++) {
            const uint32_t koff = sbase + ks * 32;   // 16 halves = 32 bytes
            uint32_t af[2][4], bf[8][2];
            ldsm_x4(af[0][0], af[0][1], af[0][2], af[0][3], a_base0 + koff);
            ldsm_x4(af[1][0], af[1][1], af[1][2], af[1][3], a_base1 + koff);
            #pragma unroll
            for (int q = 0; q < 4; q++)
                ldsm_x4(bf[2 * q][0], bf[2 * q][1], bf[2 * q + 1][0], bf[2 * q + 1][1],
                        b_base[q] + koff);
            #pragma unroll
            for (int mt = 0; mt < 2; mt++)
                #pragma unroll
                for (int nt = 0; nt < 8; nt++)
                    mma_f16(acc[mt][nt], af[mt], bf[nt]);
        }
        __syncthreads();
    }

    // ---- epilogue ----
    #pragma unroll
    for (int mt = 0; mt < 2; mt++) {
        #pragma unroll
        for (int nt = 0; nt < 8; nt++) {
            int col = bn + wn + nt * 8 + 2 * c;
            float b0 = __ldg(bias + col), b1 = __ldg(bias + col + 1);
            int row0 = bm + wm + mt * 16 + r;
            int row1 = row0 + 8;
            float v0 = acc[mt][nt][0] + b0, v1 = acc[mt][nt][1] + b1;
            float v2 = acc[mt][nt][2] + b0, v3 = acc[mt][nt][3] + b1;
            if (RELU) {
                v0 = fmaxf(v0, 0.f); v1 = fmaxf(v1, 0.f);
                v2 = fmaxf(v2, 0.f); v3 = fmaxf(v3, 0.f);
            }
            if (HALF_OUT) {
                __half* Ch = (__half*)Cv;
                if (row0 < M) *(__half2*)(Ch + (size_t)row0 * N + col) = __floats2half2_rn(v0, v1);
                if (row1 < M) *(__half2*)(Ch + (size_t)row1 * N + col) = __floats2half2_rn(v2, v3);
            } else {
                float* Cf = (float*)Cv;
                if (row0 < M) *(float2*)(Cf + (size_t)row0 * N + col) = make_float2(v0, v1);
                if (row1 < M) *(float2*)(Cf + (size_t)row1 * N + col) = make_float2(v2, v3);
            }
        }
    }
}

// ---------------- deformable sampling: 2 heads per warp, half2 gathers ----------------
__global__ void __launch_bounds__(128) sample_kernel(const float* __restrict__ rp, int T)
{
    const int t = blockIdx.x;
    if (t >= T) return;
    const int warp = threadIdx.x >> 5;
    const int lane = threadIdx.x & 31;
    const unsigned FULL = 0xffffffffu;

    const int p = lane & 15;
    const int h = warp * 2 + (lane >> 4);

    const float* raw = g_offattn + (size_t)t * 384;

    float2 off = *(const float2*)(raw + h * 32 + p * 2);
    float av = raw[256 + h * 16 + p];
    float m = av;
    #pragma unroll
    for (int o = 8; o; o >>= 1) m = fmaxf(m, __shfl_xor_sync(FULL, m, o));
    float e = __expf(av - m);
    float s = e;
    #pragma unroll
    for (int o = 8; o; o >>= 1) s += __shfl_xor_sync(FULL, s, o);
    const float anorm = e / s;

    const int LSa[4] = {0, 10000, 12500, 13125};
    const int Wla[4] = {100, 50, 25, 13};
    const int l = p >> 2;
    const int Wi = Wla[l];
    const float rx = __ldg(rp + (size_t)t * 8 + 2 * l);
    const float ry = __ldg(rp + (size_t)t * 8 + 2 * l + 1);

    float x = rx * (float)Wi + off.x - 0.5f;
    float y = ry * (float)Wi + off.y - 0.5f;
    float xf = floorf(x), yf = floorf(y);
    int x0 = (int)xf, y0 = (int)yf;
    float wx1 = x - xf, wy1 = y - yf;
    float wx0 = 1.f - wx1, wy0 = 1.f - wy1;

    int   idxs[4];
    float ws[4];
    #pragma unroll
    for (int tap = 0; tap < 4; tap++) {
        int dx = tap & 1, dy = tap >> 1;
        int xi = x0 + dx, yi = y0 + dy;
        bool valid = (xi >= 0) & (xi < Wi) & (yi >= 0) & (yi < Wi);
        float w = (dx ? wx1 : wx0) * (dy ? wy1 : wy0) * anorm;
        int xic = min(max(xi, 0), Wi - 1);
        int yic = min(max(yi, 0), Wi - 1);
        idxs[tap] = LSa[l] + yic * Wi + xic;
        ws[tap] = valid ? w : 0.f;
    }

    const int n = (t >= LQ) ? 1 : 0;
    const int ch = p * 2;
    const size_t hbase = ((size_t)n * LQ) * 256 + h * 32 + ch;
    const __half2* vb = (const __half2*)g_value_h + (hbase >> 1);

    float2 a0 = {0.f, 0.f}, a1 = {0.f, 0.f}, a2 = {0.f, 0.f}, a3 = {0.f, 0.f};
    const int lbase = lane & 16;
    #pragma unroll
    for (int pi = 0; pi < 16; pi++) {
        const int sl = lbase + pi;
        int i0 = __shfl_sync(FULL, idxs[0], sl);
        int i1 = __shfl_sync(FULL, idxs[1], sl);
        int i2 = __shfl_sync(FULL, idxs[2], sl);
        int i3 = __shfl_sync(FULL, idxs[3], sl);
        float w0 = __shfl_sync(FULL, ws[0], sl);
        float w1 = __shfl_sync(FULL, ws[1], sl);
        float w2 = __shfl_sync(FULL, ws[2], sl);
        float w3 = __shfl_sync(FULL, ws[3], sl);
        float2 v0 = __half22float2(__ldg(vb + (size_t)i0 * 128));
        float2 v1 = __half22float2(__ldg(vb + (size_t)i1 * 128));
        float2 v2 = __half22float2(__ldg(vb + (size_t)i2 * 128));
        float2 v3 = __half22float2(__ldg(vb + (size_t)i3 * 128));
        a0.x = fmaf(w0, v0.x, a0.x); a0.y = fmaf(w0, v0.y, a0.y);
        a1.x = fmaf(w1, v1.x, a1.x); a1.y = fmaf(w1, v1.y, a1.y);
        a2.x = fmaf(w2, v2.x, a2.x); a2.y = fmaf(w2, v2.y, a2.y);
        a3.x = fmaf(w3, v3.x, a3.x); a3.y = fmaf(w3, v3.y, a3.y);
    }
    float ox = (a0.x + a1.x) + (a2.x + a3.x);
    float oy = (a0.y + a1.y) + (a2.y + a3.y);
    __half2* outp = (__half2*)g_samp_h + (((size_t)t * 256 + h * 32 + ch) >> 1);
    *outp = __floats2half2_rn(ox, oy);
}

// ---------------- LayerNorm: one warp per token, out = LN(a+b)*g + be ----------------
template<bool WRITEH>
__global__ void __launch_bounds__(256) ln_kernel(
    const float* __restrict__ a, const float* __restrict__ b,
    const float* __restrict__ g, const float* __restrict__ be,
    float* __restrict__ out, __half* __restrict__ outh, int T)
{
    const int warp = (blockIdx.x * blockDim.x + threadIdx.x) >> 5;
    if (warp >= T) return;
    const int lane = threadIdx.x & 31;
    const size_t base = (size_t)warp * 256 + lane * 8;

    float4 a0 = *(const float4*)(a + base);
    float4 a1 = *(const float4*)(a + base + 4);
    float4 b0 = *(const float4*)(b + base);
    float4 b1 = *(const float4*)(b + base + 4);
    float v[8] = {a0.x + b0.x, a0.y + b0.y, a0.z + b0.z, a0.w + b0.w,
                  a1.x + b1.x, a1.y + b1.y, a1.z + b1.z, a1.w + b1.w};
    float s = 0.f, s2 = 0.f;
    #pragma unroll
    for (int i = 0; i < 8; i++) { s += v[i]; s2 = fmaf(v[i], v[i], s2); }
    #pragma unroll
    for (int o = 16; o; o >>= 1) {
        s  += __shfl_xor_sync(0xffffffffu, s,  o);
        s2 += __shfl_xor_sync(0xffffffffu, s2, o);
    }
    float mu = s * (1.f / 256.f);
    float var = s2 * (1.f / 256.f) - mu * mu;
    float rstd = rsqrtf(var + 1e-5f);

    float4 gg0 = *(const float4*)(g + lane * 8);
    float4 gg1 = *(const float4*)(g + lane * 8 + 4);
    float4 bb0 = *(const float4*)(be + lane * 8);
    float4 bb1 = *(const float4*)(be + lane * 8 + 4);
    float gv[8] = {gg0.x, gg0.y, gg0.z, gg0.w, gg1.x, gg1.y, gg1.z, gg1.w};
    float bv[8] = {bb0.x, bb0.y, bb0.z, bb0.w, bb1.x, bb1.y, bb1.z, bb1.w};
    float o0[8];
    #pragma unroll
    for (int i = 0; i < 8; i++) o0[i] = (v[i] - mu) * rstd * gv[i] + bv[i];
    *(float4*)(out + base)     = make_float4(o0[0], o0[1], o0[2], o0[3]);
    *(float4*)(out + base + 4) = make_float4(o0[4], o0[5], o0[6], o0[7]);
    if (WRITEH) {
        __half2* oh = (__half2*)(outh + base);
        oh[0] = __floats2half2_rn(o0[0], o0[1]);
        oh[1] = __floats2half2_rn(o0[2], o0[3]);
        oh[2] = __floats2half2_rn(o0[4], o0[5]);
        oh[3] = __floats2half2_rn(o0[6], o0[7]);
    }
}

// ---------------- host launcher ----------------
extern "C" void kernel_launch(void* const* d_in, const int* in_sizes, int n_in,
                              void* d_out, int out_size)
{
    const float* src   = (const float*)d_in[0];
    const float* pos   = (const float*)d_in[1];
    const float* rp    = (const float*)d_in[2];
    const float* Wv    = (const float*)d_in[5];
    const float* bv    = (const float*)d_in[6];
    const float* Woff  = (const float*)d_in[7];
    const float* boff  = (const float*)d_in[8];
    const float* Wattn = (const float*)d_in[9];
    const float* battn = (const float*)d_in[10];
    const float* Wout  = (const float*)d_in[11];
    const float* bout  = (const float*)d_in[12];
    const float* W1    = (const float*)d_in[13];
    const float* b1    = (const float*)d_in[14];
    const float* W2    = (const float*)d_in[15];
    const float* b2    = (const float*)d_in[16];
    const float* g1    = (const float*)d_in[17];
    const float* be1   = (const float*)d_in[18];
    const float* g2    = (const float*)d_in[19];
    const float* be2   = (const float*)d_in[20];

    const int T = in_sizes[0] / DMODEL;   // N * Lq

    float  *p_offattn, *p_x, *p_x2, *p_f, *p_bpack;
    __half *p_value_h, *p_src_h, *p_q_h, *p_samp_h, *p_x_h, *p_h_h;
    __half *p_Wvt, *p_Wpackt, *p_Woutt, *p_W1t, *p_W2t;
    cudaGetSymbolAddress((void**)&p_offattn, g_offattn);
    cudaGetSymbolAddress((void**)&p_x,       g_x);
    cudaGetSymbolAddress((void**)&p_x2,      g_x2);
    cudaGetSymbolAddress((void**)&p_f,       g_fbuf);
    cudaGetSymbolAddress((void**)&p_bpack,   g_bpack);
    cudaGetSymbolAddress((void**)&p_value_h, g_value_h);
    cudaGetSymbolAddress((void**)&p_src_h,   g_src_h);
    cudaGetSymbolAddress((void**)&p_q_h,     g_q_h);
    cudaGetSymbolAddress((void**)&p_samp_h,  g_samp_h);
    cudaGetSymbolAddress((void**)&p_x_h,     g_x_h);
    cudaGetSymbolAddress((void**)&p_h_h,     g_h_h);
    cudaGetSymbolAddress((void**)&p_Wvt,     g_Wvt);
    cudaGetSymbolAddress((void**)&p_Wpackt,  g_Wpackt);
    cudaGetSymbolAddress((void**)&p_Woutt,   g_Woutt);
    cudaGetSymbolAddress((void**)&p_W1t,     g_W1t);
    cudaGetSymbolAddress((void**)&p_W2t,     g_W2t);

    cudaFuncSetAttribute(hgemm_kernel<false, false>, cudaFuncAttributeMaxDynamicSharedMemorySize, GEMM_DSMEM);
    cudaFuncSetAttribute(hgemm_kernel<false, true>,  cudaFuncAttributeMaxDynamicSharedMemorySize, GEMM_DSMEM);
    cudaFuncSetAttribute(hgemm_kernel<true,  true>,  cudaFuncAttributeMaxDynamicSharedMemorySize, GEMM_DSMEM);

    const int MB = (T + 127) / 128;
    const int n4 = T * DMODEL / 4;
    dim3 tb(32, 8);

    // ---- prep (2 launches) ----
    prep_w_kernel<<<738, tb>>>(Wv, Woff, Wout, Wattn, W1, W2, boff, battn);
    prep_act_kernel<<<(n4 + 255) / 256, 256>>>(src, pos, n4);

    // 1. value = src @ Wv + bv            (half out, sampling source)
    hgemm_kernel<false, true><<<dim3(2, MB), 256, GEMM_DSMEM>>>(p_src_h, p_Wvt, bv, p_value_h, T, 256, 256);

    // 2. offattn = q @ [W_off|W_attn] + b (f32 out)
    hgemm_kernel<false, false><<<dim3(3, MB), 256, GEMM_DSMEM>>>(p_q_h, p_Wpackt, p_bpack, p_offattn, T, 384, 256);

    // 3. deformable sampling + softmax fused (half out)
    sample_kernel<<<T, 128>>>(rp, T);

    // 4. x2 = samp @ W_out + b_out        (f32 out)
    hgemm_kernel<false, false><<<dim3(2, MB), 256, GEMM_DSMEM>>>(p_samp_h, p_Woutt, bout, p_x2, T, 256, 256);

    // 5. x = LN(src + x2)                 (f32 + half)
    ln_kernel<true><<<(T * 32 + 255) / 256, 256>>>(src, p_x2, g1, be1, p_x, p_x_h, T);

    // 6. h = relu(x @ W1 + b1)            (half out only)
    hgemm_kernel<true, true><<<dim3(8, MB), 256, GEMM_DSMEM>>>(p_x_h, p_W1t, b1, p_h_h, T, 1024, 256);

    // 7. f = h @ W2 + b2                  (f32 out)
    hgemm_kernel<false, false><<<dim3(2, MB), 256, GEMM_DSMEM>>>(p_h_h, p_W2t, b2, p_f, T, 256, 1024);

    // 8. out = LN(x + f)
    ln_kernel<false><<<(T * 32 + 255) / 256, 256>>>(p_x, p_f, g2, be2, (float*)d_out, nullptr, T);
}

// round 10
// speedup vs baseline: 5.2427x; 1.1054x over previous
#include <cuda_runtime.h>
#include <cuda_fp16.h>
#include <math.h>
#include <stdint.h>

#define LQ 13294
#define DMODEL 256
#define MAXN 2

// ---------------- scratch (device globals; no allocation) ----------------
__device__ float  g_offattn[MAXN*LQ*384];      // [T,384] f32
__device__ float  g_x[MAXN*LQ*DMODEL];         // [T,256] f32 (residual)
__device__ float  g_x2[MAXN*LQ*DMODEL];        // [T,256] f32
__device__ float  g_fbuf[MAXN*LQ*DMODEL];      // [T,256] f32
__device__ __half g_value_h[MAXN*LQ*DMODEL];   // [T,256] half (sampling source)
__device__ __half g_src_h[MAXN*LQ*DMODEL];     // half GEMM inputs
__device__ __half g_q_h[MAXN*LQ*DMODEL];
__device__ __half g_samp_h[MAXN*LQ*DMODEL];
__device__ __half g_x_h[MAXN*LQ*DMODEL];
__device__ __half g_h_h[MAXN*LQ*1024];         // FFN intermediate, half only
// transposed half weights [N][K]
__device__ __half g_Wvt[256*256];
__device__ __half g_Wpackt[384*256];
__device__ __half g_Woutt[256*256];
__device__ __half g_W1t[1024*256];
__device__ __half g_W2t[256*1024];
__device__ float  g_bpack[384];

// ---------------- prep: all weight transposes + bias pack in ONE kernel ----------------
__device__ __forceinline__ void do_transpose(const float* in, __half* out, int R, int C,
                                             int bx, int by) {
    __shared__ float tile[32][33];
    int x = bx + threadIdx.x;
    #pragma unroll
    for (int i = 0; i < 4; i++) {
        int y = by + threadIdx.y + i * 8;
        if (y < R && x < C) tile[threadIdx.y + i * 8][threadIdx.x] = in[(size_t)y * C + x];
    }
    __syncthreads();
    int xo = by + threadIdx.x;
    #pragma unroll
    for (int i = 0; i < 4; i++) {
        int yo = bx + threadIdx.y + i * 8;
        if (yo < C && xo < R) out[(size_t)yo * R + xo] = __float2half(tile[threadIdx.x][threadIdx.y + i * 8]);
    }
}

__global__ void prep_w_kernel(const float* __restrict__ Wv, const float* __restrict__ Woff,
                              const float* __restrict__ Wout, const float* __restrict__ Wattn,
                              const float* __restrict__ W1, const float* __restrict__ W2,
                              const float* __restrict__ boff, const float* __restrict__ battn) {
    int id = blockIdx.x;
    if (id < 64)       do_transpose(Wv,   g_Wvt,            256, 256,  (id & 7) * 32,          (id >> 3) * 32);
    else if (id < 128) do_transpose(Woff, g_Wpackt,         256, 256,  ((id - 64) & 7) * 32,   ((id - 64) >> 3) * 32);
    else if (id < 192) do_transpose(Wout, g_Woutt,          256, 256,  ((id - 128) & 7) * 32,  ((id - 128) >> 3) * 32);
    else if (id < 224) do_transpose(Wattn, g_Wpackt + 65536, 256, 128, ((id - 192) & 3) * 32,  ((id - 192) >> 2) * 32);
    else if (id < 480) do_transpose(W1,   g_W1t,            256, 1024, ((id - 224) & 31) * 32, ((id - 224) >> 5) * 32);
    else if (id < 736) do_transpose(W2,   g_W2t,            1024, 256, ((id - 480) & 7) * 32,  ((id - 480) >> 3) * 32);
    else {
        int tid = threadIdx.y * 32 + threadIdx.x;
        if (id == 736) g_bpack[tid] = boff[tid];
        else if (tid < 128) g_bpack[256 + tid] = battn[tid];
    }
}

__global__ void prep_act_kernel(const float* __restrict__ src, const float* __restrict__ pos,
                                int n4) {
    int i = blockIdx.x * blockDim.x + threadIdx.x;
    if (i < n4) {
        float4 vs = ((const float4*)src)[i];
        float4 vp = ((const float4*)pos)[i];
        __half2* os = (__half2*)g_src_h;
        __half2* oq = (__half2*)g_q_h;
        os[2 * i]     = __floats2half2_rn(vs.x, vs.y);
        os[2 * i + 1] = __floats2half2_rn(vs.z, vs.w);
        oq[2 * i]     = __floats2half2_rn(vs.x + vp.x, vs.y + vp.y);
        oq[2 * i + 1] = __floats2half2_rn(vs.z + vp.z, vs.w + vp.w);
    }
}

// ---------------- fp16 tensor-core GEMM (m16n8k16, fp32 accum, ldmatrix) ----------------
// BM=128, BN=128, BK=64, 256 threads = 8 warps (4M x 2N), warp tile 32x64.
// 3-stage cp.async ring, prefetch distance 2, ONE __syncthreads per k-tile.

__device__ __forceinline__ void mma_f16(float* d, const uint32_t* a, const uint32_t* b) {
    asm volatile(
        "mma.sync.aligned.m16n8k16.row.col.f32.f16.f16.f32 "
        "{%0,%1,%2,%3}, {%4,%5,%6,%7}, {%8,%9}, {%0,%1,%2,%3};\n"
        : "+f"(d[0]), "+f"(d[1]), "+f"(d[2]), "+f"(d[3])
        : "r"(a[0]), "r"(a[1]), "r"(a[2]), "r"(a[3]), "r"(b[0]), "r"(b[1]));
}

__device__ __forceinline__ void ldsm_x4(uint32_t& r0, uint32_t& r1, uint32_t& r2, uint32_t& r3,
                                        uint32_t addr) {
    asm volatile("ldmatrix.sync.aligned.m8n8.x4.shared.b16 {%0,%1,%2,%3}, [%4];"
                 : "=r"(r0), "=r"(r1), "=r"(r2), "=r"(r3) : "r"(addr));
}

__device__ __forceinline__ void cp_async16(uint32_t saddr, const void* gptr, int srcbytes) {
    asm volatile("cp.async.cg.shared.global [%0], [%1], 16, %2;\n"
                 :: "r"(saddr), "l"(gptr), "r"(srcbytes));
}
__device__ __forceinline__ void cp_commit() { asm volatile("cp.async.commit_group;\n"); }
template<int N>
__device__ __forceinline__ void cp_wait() { asm volatile("cp.async.wait_group %0;\n" :: "n"(N)); }

#define BK 64
#define HSTRIDE 72                           // halves per row (144B; 16B-rotation mod 128 -> conflict-free)
#define TILE_H (128*HSTRIDE)                 // 9216 halves
#define STAGE_BYTES (2*TILE_H*2)             // 36864 B
#define NSTAGE 3
#define GEMM_DSMEM (NSTAGE*STAGE_BYTES)      // 110592 B

template<bool RELU, bool HALF_OUT>
__global__ void __launch_bounds__(256) hgemm_kernel(
    const __half* __restrict__ A, const __half* __restrict__ Bt,
    const float* __restrict__ bias, void* __restrict__ Cv,
    int M, int N, int K)
{
    extern __shared__ __align__(16) char smem_raw[];
    const uint32_t smem_u = (uint32_t)__cvta_generic_to_shared(smem_raw);

    const int tid = threadIdx.x;
    const int wid = tid >> 5;
    const int lane = tid & 31;
    const int bm = blockIdx.y * 128;
    const int bn = blockIdx.x * 128;
    const int wm = (wid & 3) * 32;
    const int wn = (wid >> 2) * 64;
    const int r = lane >> 2;
    const int c = lane & 3;

    // ldmatrix per-lane base addresses (stage 0, ks 0)
    const int mrow = lane & 7;
    const int mid = lane >> 3;
    const uint32_t a_base0 = smem_u + (uint32_t)(((wm + (mid & 1) * 8 + mrow) * HSTRIDE + (mid >> 1) * 8) * 2);
    const uint32_t a_base1 = a_base0 + 16 * HSTRIDE * 2;
    uint32_t b_base[4];
    #pragma unroll
    for (int q = 0; q < 4; q++)
        b_base[q] = smem_u + TILE_H * 2 +
                    (uint32_t)(((wn + q * 16 + (mid >> 1) * 8 + mrow) * HSTRIDE + (mid & 1) * 8) * 2);

    float acc[2][8][4];
    #pragma unroll
    for (int i = 0; i < 2; i++)
        #pragma unroll
        for (int j = 0; j < 8; j++)
            #pragma unroll
            for (int k = 0; k < 4; k++) acc[i][j][k] = 0.f;

    const int ktiles = K / BK;               // >= 4 for all our GEMMs

    // load geometry: 128 rows x 8 chunks(16B) = 1024 chunks; 256 thr -> 4 each
    auto issue_tile = [&](int kt, int s) {
        const int kk = kt * BK;
        const uint32_t sb = smem_u + s * STAGE_BYTES;
        #pragma unroll
        for (int i = 0; i < 4; i++) {
            int idx = tid + i * 256;
            int row = idx >> 3, ch = idx & 7;
            int gr = bm + row;
            cp_async16(sb + (row * HSTRIDE + ch * 8) * 2,
                       A + (size_t)gr * K + kk + ch * 8, (gr < M) ? 16 : 0);
        }
        const uint32_t bb = sb + TILE_H * 2;
        #pragma unroll
        for (int i = 0; i < 4; i++) {
            int idx = tid + i * 256;
            int row = idx >> 3, ch = idx & 7;
            cp_async16(bb + (row * HSTRIDE + ch * 8) * 2,
                       Bt + (size_t)(bn + row) * K + kk + ch * 8, 16);
        }
        cp_commit();
    };

    issue_tile(0, 0);
    issue_tile(1, 1);

    for (int kt = 0; kt < ktiles; kt++) {
        const int cur = kt % 3;
        cp_wait<1>();
        __syncthreads();    // all warps done computing kt-1; stage (kt+2)%3 == (kt-1)%3 is dead

        if (kt + 2 < ktiles) issue_tile(kt + 2, (kt + 2) % 3);
        else cp_commit();   // keep group accounting

        const uint32_t sbase = (uint32_t)(cur * STAGE_BYTES);

        #pragma unroll
        for (int ks = 0; ks < 4; ks++) {
            const uint32_t koff = sbase + ks * 32;   // 16 halves = 32 B
            uint32_t af[2][4], bf[8][2];
            ldsm_x4(af[0][0], af[0][1], af[0][2], af[0][3], a_base0 + koff);
            ldsm_x4(af[1][0], af[1][1], af[1][2], af[1][3], a_base1 + koff);
            #pragma unroll
            for (int q = 0; q < 4; q++)
                ldsm_x4(bf[2 * q][0], bf[2 * q][1], bf[2 * q + 1][0], bf[2 * q + 1][1],
                        b_base[q] + koff);
            #pragma unroll
            for (int mt = 0; mt < 2; mt++)
                #pragma unroll
                for (int nt = 0; nt < 8; nt++)
                    mma_f16(acc[mt][nt], af[mt], bf[nt]);
        }
    }

    // ---- epilogue ----
    #pragma unroll
    for (int mt = 0; mt < 2; mt++) {
        #pragma unroll
        for (int nt = 0; nt < 8; nt++) {
            int col = bn + wn + nt * 8 + 2 * c;
            float b0 = __ldg(bias + col), b1 = __ldg(bias + col + 1);
            int row0 = bm + wm + mt * 16 + r;
            int row1 = row0 + 8;
            float v0 = acc[mt][nt][0] + b0, v1 = acc[mt][nt][1] + b1;
            float v2 = acc[mt][nt][2] + b0, v3 = acc[mt][nt][3] + b1;
            if (RELU) {
                v0 = fmaxf(v0, 0.f); v1 = fmaxf(v1, 0.f);
                v2 = fmaxf(v2, 0.f); v3 = fmaxf(v3, 0.f);
            }
            if (HALF_OUT) {
                __half* Ch = (__half*)Cv;
                if (row0 < M) *(__half2*)(Ch + (size_t)row0 * N + col) = __floats2half2_rn(v0, v1);
                if (row1 < M) *(__half2*)(Ch + (size_t)row1 * N + col) = __floats2half2_rn(v2, v3);
            } else {
                float* Cf = (float*)Cv;
                if (row0 < M) *(float2*)(Cf + (size_t)row0 * N + col) = make_float2(v0, v1);
                if (row1 < M) *(float2*)(Cf + (size_t)row1 * N + col) = make_float2(v2, v3);
            }
        }
    }
}

// ---------------- deformable sampling: 2 heads per warp, half2 gathers ----------------
__global__ void __launch_bounds__(128) sample_kernel(const float* __restrict__ rp, int T)
{
    const int t = blockIdx.x;
    if (t >= T) return;
    const int warp = threadIdx.x >> 5;
    const int lane = threadIdx.x & 31;
    const unsigned FULL = 0xffffffffu;

    const int p = lane & 15;
    const int h = warp * 2 + (lane >> 4);

    const float* raw = g_offattn + (size_t)t * 384;

    float2 off = *(const float2*)(raw + h * 32 + p * 2);
    float av = raw[256 + h * 16 + p];
    float m = av;
    #pragma unroll
    for (int o = 8; o; o >>= 1) m = fmaxf(m, __shfl_xor_sync(FULL, m, o));
    float e = __expf(av - m);
    float s = e;
    #pragma unroll
    for (int o = 8; o; o >>= 1) s += __shfl_xor_sync(FULL, s, o);
    const float anorm = e / s;

    const int LSa[4] = {0, 10000, 12500, 13125};
    const int Wla[4] = {100, 50, 25, 13};
    const int l = p >> 2;
    const int Wi = Wla[l];
    const float rx = __ldg(rp + (size_t)t * 8 + 2 * l);
    const float ry = __ldg(rp + (size_t)t * 8 + 2 * l + 1);

    float x = rx * (float)Wi + off.x - 0.5f;
    float y = ry * (float)Wi + off.y - 0.5f;
    float xf = floorf(x), yf = floorf(y);
    int x0 = (int)xf, y0 = (int)yf;
    float wx1 = x - xf, wy1 = y - yf;
    float wx0 = 1.f - wx1, wy0 = 1.f - wy1;

    int   idxs[4];
    float ws[4];
    #pragma unroll
    for (int tap = 0; tap < 4; tap++) {
        int dx = tap & 1, dy = tap >> 1;
        int xi = x0 + dx, yi = y0 + dy;
        bool valid = (xi >= 0) & (xi < Wi) & (yi >= 0) & (yi < Wi);
        float w = (dx ? wx1 : wx0) * (dy ? wy1 : wy0) * anorm;
        int xic = min(max(xi, 0), Wi - 1);
        int yic = min(max(yi, 0), Wi - 1);
        idxs[tap] = LSa[l] + yic * Wi + xic;
        ws[tap] = valid ? w : 0.f;
    }

    const int n = (t >= LQ) ? 1 : 0;
    const int ch = p * 2;
    const size_t hbase = ((size_t)n * LQ) * 256 + h * 32 + ch;
    const __half2* vb = (const __half2*)g_value_h + (hbase >> 1);

    float2 a0 = {0.f, 0.f}, a1 = {0.f, 0.f}, a2 = {0.f, 0.f}, a3 = {0.f, 0.f};
    const int lbase = lane & 16;
    #pragma unroll
    for (int pi = 0; pi < 16; pi++) {
        const int sl = lbase + pi;
        int i0 = __shfl_sync(FULL, idxs[0], sl);
        int i1 = __shfl_sync(FULL, idxs[1], sl);
        int i2 = __shfl_sync(FULL, idxs[2], sl);
        int i3 = __shfl_sync(FULL, idxs[3], sl);
        float w0 = __shfl_sync(FULL, ws[0], sl);
        float w1 = __shfl_sync(FULL, ws[1], sl);
        float w2 = __shfl_sync(FULL, ws[2], sl);
        float w3 = __shfl_sync(FULL, ws[3], sl);
        float2 v0 = __half22float2(__ldg(vb + (size_t)i0 * 128));
        float2 v1 = __half22float2(__ldg(vb + (size_t)i1 * 128));
        float2 v2 = __half22float2(__ldg(vb + (size_t)i2 * 128));
        float2 v3 = __half22float2(__ldg(vb + (size_t)i3 * 128));
        a0.x = fmaf(w0, v0.x, a0.x); a0.y = fmaf(w0, v0.y, a0.y);
        a1.x = fmaf(w1, v1.x, a1.x); a1.y = fmaf(w1, v1.y, a1.y);
        a2.x = fmaf(w2, v2.x, a2.x); a2.y = fmaf(w2, v2.y, a2.y);
        a3.x = fmaf(w3, v3.x, a3.x); a3.y = fmaf(w3, v3.y, a3.y);
    }
    float ox = (a0.x + a1.x) + (a2.x + a3.x);
    float oy = (a0.y + a1.y) + (a2.y + a3.y);
    __half2* outp = (__half2*)g_samp_h + (((size_t)t * 256 + h * 32 + ch) >> 1);
    *outp = __floats2half2_rn(ox, oy);
}

// ---------------- LayerNorm: one warp per token, out = LN(a+b)*g + be ----------------
template<bool WRITEH>
__global__ void __launch_bounds__(256) ln_kernel(
    const float* __restrict__ a, const float* __restrict__ b,
    const float* __restrict__ g, const float* __restrict__ be,
    float* __restrict__ out, __half* __restrict__ outh, int T)
{
    const int warp = (blockIdx.x * blockDim.x + threadIdx.x) >> 5;
    if (warp >= T) return;
    const int lane = threadIdx.x & 31;
    const size_t base = (size_t)warp * 256 + lane * 8;

    float4 a0 = *(const float4*)(a + base);
    float4 a1 = *(const float4*)(a + base + 4);
    float4 b0 = *(const float4*)(b + base);
    float4 b1 = *(const float4*)(b + base + 4);
    float v[8] = {a0.x + b0.x, a0.y + b0.y, a0.z + b0.z, a0.w + b0.w,
                  a1.x + b1.x, a1.y + b1.y, a1.z + b1.z, a1.w + b1.w};
    float s = 0.f, s2 = 0.f;
    #pragma unroll
    for (int i = 0; i < 8; i++) { s += v[i]; s2 = fmaf(v[i], v[i], s2); }
    #pragma unroll
    for (int o = 16; o; o >>= 1) {
        s  += __shfl_xor_sync(0xffffffffu, s,  o);
        s2 += __shfl_xor_sync(0xffffffffu, s2, o);
    }
    float mu = s * (1.f / 256.f);
    float var = s2 * (1.f / 256.f) - mu * mu;
    float rstd = rsqrtf(var + 1e-5f);

    float4 gg0 = *(const float4*)(g + lane * 8);
    float4 gg1 = *(const float4*)(g + lane * 8 + 4);
    float4 bb0 = *(const float4*)(be + lane * 8);
    float4 bb1 = *(const float4*)(be + lane * 8 + 4);
    float gv[8] = {gg0.x, gg0.y, gg0.z, gg0.w, gg1.x, gg1.y, gg1.z, gg1.w};
    float bv[8] = {bb0.x, bb0.y, bb0.z, bb0.w, bb1.x, bb1.y, bb1.z, bb1.w};
    float o0[8];
    #pragma unroll
    for (int i = 0; i < 8; i++) o0[i] = (v[i] - mu) * rstd * gv[i] + bv[i];
    *(float4*)(out + base)     = make_float4(o0[0], o0[1], o0[2], o0[3]);
    *(float4*)(out + base + 4) = make_float4(o0[4], o0[5], o0[6], o0[7]);
    if (WRITEH) {
        __half2* oh = (__half2*)(outh + base);
        oh[0] = __floats2half2_rn(o0[0], o0[1]);
        oh[1] = __floats2half2_rn(o0[2], o0[3]);
        oh[2] = __floats2half2_rn(o0[4], o0[5]);
        oh[3] = __floats2half2_rn(o0[6], o0[7]);
    }
}

// ---------------- host launcher ----------------
extern "C" void kernel_launch(void* const* d_in, const int* in_sizes, int n_in,
                              void* d_out, int out_size)
{
    const float* src   = (const float*)d_in[0];
    const float* pos   = (const float*)d_in[1];
    const float* rp    = (const float*)d_in[2];
    const float* Wv    = (const float*)d_in[5];
    const float* bv    = (const float*)d_in[6];
    const float* Woff  = (const float*)d_in[7];
    const float* boff  = (const float*)d_in[8];
    const float* Wattn = (const float*)d_in[9];
    const float* battn = (const float*)d_in[10];
    const float* Wout  = (const float*)d_in[11];
    const float* bout  = (const float*)d_in[12];
    const float* W1    = (const float*)d_in[13];
    const float* b1    = (const float*)d_in[14];
    const float* W2    = (const float*)d_in[15];
    const float* b2    = (const float*)d_in[16];
    const float* g1    = (const float*)d_in[17];
    const float* be1   = (const float*)d_in[18];
    const float* g2    = (const float*)d_in[19];
    const float* be2   = (const float*)d_in[20];

    const int T = in_sizes[0] / DMODEL;   // N * Lq

    float  *p_offattn, *p_x, *p_x2, *p_f, *p_bpack;
    __half *p_value_h, *p_src_h, *p_q_h, *p_samp_h, *p_x_h, *p_h_h;
    __half *p_Wvt, *p_Wpackt, *p_Woutt, *p_W1t, *p_W2t;
    cudaGetSymbolAddress((void**)&p_offattn, g_offattn);
    cudaGetSymbolAddress((void**)&p_x,       g_x);
    cudaGetSymbolAddress((void**)&p_x2,      g_x2);
    cudaGetSymbolAddress((void**)&p_f,       g_fbuf);
    cudaGetSymbolAddress((void**)&p_bpack,   g_bpack);
    cudaGetSymbolAddress((void**)&p_value_h, g_value_h);
    cudaGetSymbolAddress((void**)&p_src_h,   g_src_h);
    cudaGetSymbolAddress((void**)&p_q_h,     g_q_h);
    cudaGetSymbolAddress((void**)&p_samp_h,  g_samp_h);
    cudaGetSymbolAddress((void**)&p_x_h,     g_x_h);
    cudaGetSymbolAddress((void**)&p_h_h,     g_h_h);
    cudaGetSymbolAddress((void**)&p_Wvt,     g_Wvt);
    cudaGetSymbolAddress((void**)&p_Wpackt,  g_Wpackt);
    cudaGetSymbolAddress((void**)&p_Woutt,   g_Woutt);
    cudaGetSymbolAddress((void**)&p_W1t,     g_W1t);
    cudaGetSymbolAddress((void**)&p_W2t,     g_W2t);

    cudaFuncSetAttribute(hgemm_kernel<false, false>, cudaFuncAttributeMaxDynamicSharedMemorySize, GEMM_DSMEM);
    cudaFuncSetAttribute(hgemm_kernel<false, true>,  cudaFuncAttributeMaxDynamicSharedMemorySize, GEMM_DSMEM);
    cudaFuncSetAttribute(hgemm_kernel<true,  true>,  cudaFuncAttributeMaxDynamicSharedMemorySize, GEMM_DSMEM);

    const int MB = (T + 127) / 128;
    const int n4 = T * DMODEL / 4;
    dim3 tb(32, 8);

    // ---- prep (2 launches) ----
    prep_w_kernel<<<738, tb>>>(Wv, Woff, Wout, Wattn, W1, W2, boff, battn);
    prep_act_kernel<<<(n4 + 255) / 256, 256>>>(src, pos, n4);

    // 1. value = src @ Wv + bv            (half out, sampling source)
    hgemm_kernel<false, true><<<dim3(2, MB), 256, GEMM_DSMEM>>>(p_src_h, p_Wvt, bv, p_value_h, T, 256, 256);

    // 2. offattn = q @ [W_off|W_attn] + b (f32 out)
    hgemm_kernel<false, false><<<dim3(3, MB), 256, GEMM_DSMEM>>>(p_q_h, p_Wpackt, p_bpack, p_offattn, T, 384, 256);

    // 3. deformable sampling + softmax fused (half out)
    sample_kernel<<<T, 128>>>(rp, T);

    // 4. x2 = samp @ W_out + b_out        (f32 out)
    hgemm_kernel<false, false><<<dim3(2, MB), 256, GEMM_DSMEM>>>(p_samp_h, p_Woutt, bout, p_x2, T, 256, 256);

    // 5. x = LN(src + x2)                 (f32 + half)
    ln_kernel<true><<<(T * 32 + 255) / 256, 256>>>(src, p_x2, g1, be1, p_x, p_x_h, T);

    // 6. h = relu(x @ W1 + b1)            (half out only)
    hgemm_kernel<true, true><<<dim3(8, MB), 256, GEMM_DSMEM>>>(p_x_h, p_W1t, b1, p_h_h, T, 1024, 256);

    // 7. f = h @ W2 + b2                  (f32 out)
    hgemm_kernel<false, false><<<dim3(2, MB), 256, GEMM_DSMEM>>>(p_h_h, p_W2t, b2, p_f, T, 256, 1024);

    // 8. out = LN(x + f)
    ln_kernel<false><<<(T * 32 + 255) / 256, 256>>>(p_x, p_f, g2, be2, (float*)d_out, nullptr, T);
}